// round 12
// baseline (speedup 1.0000x reference)
#include <cuda_runtime.h>
#include <cuda_fp16.h>
#include <math.h>
#include <stdint.h>

#define NN 20000
#define EE 320000
#define GG 256
#define DD 256
#define LL 5
#define EPSV 1e-5f
#define GYC 157   // (NN+127)/128

// ==================== device scratch ====================
__device__ float d_h[NN * DD];
__device__ float d_hh[NN * DD];
__device__ __half d_aggr_hi[NN * DD];
__device__ __half d_aggr_lo[NN * DD];
__device__ __half d_hid_hi[NN * 2 * DD];
__device__ __half d_hid_lo[NN * 2 * DD];
__device__ __half d_w1hi[LL * 2 * DD * DD];
__device__ __half d_w1lo[LL * 2 * DD * DD];
__device__ __half d_w2hi[LL * 2 * DD * DD];
__device__ __half d_w2lo[LL * 2 * DD * DD];
__device__ float d_scale[DD];
__device__ float d_shift[DD];
__device__ float d_gps[GYC * DD];  // gemm2 per-rowblock col-sum partials
__device__ float d_gpq[GYC * DD];  // gemm2 per-rowblock col-sumsq partials
__device__ float d_hg[GG * DD];
__device__ float d_hg2[GG * DD];
__device__ float d_pp[4 * DD];
__device__ float d_pq[4 * DD];
__device__ float d_ctab[33 * DD];
__device__ int d_deg[NN];
__device__ int d_off[NN + 1];
__device__ int d_cur[NN];
__device__ int d_csr[EE];
__device__ int d_gs[GG + 1];
__device__ int d_bsum[32];
__device__ int d_boff[32];

// ==================== PTX helpers ====================
__device__ __forceinline__ uint32_t smem_u32(const void* p) {
    uint32_t a;
    asm("{ .reg .u64 t; cvta.to.shared.u64 t, %1; cvt.u32.u64 %0, t; }" : "=r"(a) : "l"(p));
    return a;
}

__device__ __forceinline__ void ldsm_x4(uint32_t* r, uint32_t addr) {
    asm volatile("ldmatrix.sync.aligned.m8n8.x4.shared.b16 {%0,%1,%2,%3}, [%4];"
                 : "=r"(r[0]), "=r"(r[1]), "=r"(r[2]), "=r"(r[3]) : "r"(addr));
}

__device__ __forceinline__ void mma_16816(float* d, const uint32_t* a, const uint32_t* b) {
    asm volatile(
        "mma.sync.aligned.m16n8k16.row.col.f32.f16.f16.f32 "
        "{%0,%1,%2,%3}, {%4,%5,%6,%7}, {%8,%9}, {%0,%1,%2,%3};"
        : "+f"(d[0]), "+f"(d[1]), "+f"(d[2]), "+f"(d[3])
        : "r"(a[0]), "r"(a[1]), "r"(a[2]), "r"(a[3]), "r"(b[0]), "r"(b[1]));
}

__device__ __forceinline__ void cp16(uint32_t dst, const void* src, int srcsz) {
    asm volatile("cp.async.cg.shared.global [%0], [%1], 16, %2;"
                 :: "r"(dst), "l"(src), "r"(srcsz) : "memory");
}
__device__ __forceinline__ void cp_commit() {
    asm volatile("cp.async.commit_group;" ::: "memory");
}
template <int N>
__device__ __forceinline__ void cp_wait() {
    asm volatile("cp.async.wait_group %0;" :: "n"(N) : "memory");
}

__device__ __forceinline__ void acc4(float4& a, const float4 b) {
    a.x += b.x; a.y += b.y; a.z += b.z; a.w += b.w;
}
__device__ __forceinline__ float4 aff4(float4 x, const float4 sc, const float4 sh) {
    float4 r;
    r.x = fmaxf(fmaf(x.x, sc.x, sh.x), 0.f);
    r.y = fmaxf(fmaf(x.y, sc.y, sh.y), 0.f);
    r.z = fmaxf(fmaf(x.z, sc.z, sh.z), 0.f);
    r.w = fmaxf(fmaf(x.w, sc.w, sh.w), 0.f);
    return r;
}

// ==================== embeddings ====================
__global__ void embed_kernel(const int* __restrict__ xf,
                             const float* __restrict__ nt1, const float* __restrict__ nt2,
                             const float* __restrict__ nt3, const float* __restrict__ nt4,
                             const float* __restrict__ nt5, const float* __restrict__ nt6) {
    int i = blockIdx.x;
    int d = threadIdx.x;
    __shared__ int f[6];
    if (d < 6) f[d] = xf[i * 6 + d];
    __syncthreads();
    d_h[i * DD + d] = nt1[f[0] * DD + d] + nt2[f[1] * DD + d] + nt3[f[2] * DD + d]
                    + nt4[f[3] * DD + d] + nt5[f[4] * DD + d] + nt6[f[5] * DD + d];
}

// ==================== weight split fp32 -> fp16 hi/lo ====================
__global__ void wconv_kernel(const float* __restrict__ w, __half* __restrict__ hi,
                             __half* __restrict__ lo, int n) {
    int i = blockIdx.x * blockDim.x + threadIdx.x;
    if (i >= n) return;
    float v = w[i];
    __half h = __float2half_rn(v);
    hi[i] = h;
    lo[i] = __float2half_rn(v - __half2float(h));
}

// ==================== CSR build ====================
__global__ void zero_deg_kernel() {
    int i = blockIdx.x * blockDim.x + threadIdx.x;
    if (i < NN) d_deg[i] = 0;
}

__global__ void count_kernel(const int* __restrict__ ei) {
    int e = blockIdx.x * blockDim.x + threadIdx.x;
    if (e >= EE) return;
    atomicAdd(&d_deg[ei[EE + e]], 1);
}

__global__ void scan1_kernel() {
    __shared__ int wsum[32];
    int tid = threadIdx.x;
    int lane = tid & 31, w = tid >> 5;
    int idx = blockIdx.x * 1024 + tid;
    int v = (idx < NN) ? d_deg[idx] : 0;
    int x = v;
#pragma unroll
    for (int o = 1; o < 32; o <<= 1) {
        int y = __shfl_up_sync(0xffffffffu, x, o);
        if (lane >= o) x += y;
    }
    if (lane == 31) wsum[w] = x;
    __syncthreads();
    if (w == 0) {
        int s = wsum[lane];
#pragma unroll
        for (int o = 1; o < 32; o <<= 1) {
            int y = __shfl_up_sync(0xffffffffu, s, o);
            if (lane >= o) s += y;
        }
        wsum[lane] = s;
    }
    __syncthreads();
    int incl = x + ((w > 0) ? wsum[w - 1] : 0);
    if (idx < NN) d_off[idx] = incl - v;
    if (tid == 1023) d_bsum[blockIdx.x] = incl;
}

__global__ void scan2_kernel(int nblk) {
    int lane = threadIdx.x;
    int v = (lane < nblk) ? d_bsum[lane] : 0;
    int x = v;
#pragma unroll
    for (int o = 1; o < 32; o <<= 1) {
        int y = __shfl_up_sync(0xffffffffu, x, o);
        if (lane >= o) x += y;
    }
    if (lane < nblk) d_boff[lane] = x - v;
}

__global__ void scan3_kernel() {
    int idx = blockIdx.x * 1024 + threadIdx.x;
    if (idx < NN) {
        int o = d_off[idx] + d_boff[blockIdx.x];
        d_off[idx] = o;
        d_cur[idx] = o;
    }
    if (idx == 0) d_off[NN] = EE;
}

__global__ void fill_kernel(const int* __restrict__ ei, const int* __restrict__ ea) {
    int e = blockIdx.x * blockDim.x + threadIdx.x;
    if (e >= EE) return;
    int src = ei[e];
    int dst = ei[EE + e];
    int combo = (ea[e * 5 + 0] & 1) | ((ea[e * 5 + 1] & 1) << 1) | ((ea[e * 5 + 2] & 1) << 2)
              | ((ea[e * 5 + 3] & 1) << 3) | ((ea[e * 5 + 4] & 1) << 4);
    int pos = atomicAdd(&d_cur[dst], 1);
    d_csr[pos] = src | (combo << 16);
}

// ==================== per-layer combo table ====================
__global__ void ctab_kernel(int l,
                            const float* __restrict__ et1, const float* __restrict__ et2,
                            const float* __restrict__ et3, const float* __restrict__ et4,
                            const float* __restrict__ et5) {
    int c = blockIdx.x;
    int d = threadIdx.x;
    float v;
    if (c == 32) {
        v = et1[(l * 5 + 4) * DD + d] + et2[(l * 4 + 0) * DD + d] + et3[(l * 2 + 0) * DD + d]
          + et4[(l * 2 + 0) * DD + d] + et5[(l * 2 + 0) * DD + d];
    } else {
        v = et1[(l * 5 + (c & 1)) * DD + d] + et2[(l * 4 + ((c >> 1) & 1)) * DD + d]
          + et3[(l * 2 + ((c >> 2) & 1)) * DD + d] + et4[(l * 2 + ((c >> 3) & 1)) * DD + d]
          + et5[(l * 2 + ((c >> 4) & 1)) * DD + d];
    }
    d_ctab[c * DD + d] = v;
}

// ==================== SpMM: warp per node, 4-edge unroll, fused BN affine ====================
__device__ __forceinline__ void store_hilo4(__half* hi, __half* lo, float4 v) {
    __half h0 = __float2half_rn(v.x), h1 = __float2half_rn(v.y);
    __half h2 = __float2half_rn(v.z), h3 = __float2half_rn(v.w);
    ((__half2*)hi)[0] = __halves2half2(h0, h1);
    ((__half2*)hi)[1] = __halves2half2(h2, h3);
    __half l0 = __float2half_rn(v.x - __half2float(h0));
    __half l1 = __float2half_rn(v.y - __half2float(h1));
    __half l2 = __float2half_rn(v.z - __half2float(h2));
    __half l3 = __float2half_rn(v.w - __half2float(h3));
    ((__half2*)lo)[0] = __halves2half2(l0, l1);
    ((__half2*)lo)[1] = __halves2half2(l2, l3);
}

template <int APPLY>
__global__ __launch_bounds__(256) void spmm_kernel(const float* __restrict__ X) {
    int node = (blockIdx.x << 3) + (threadIdx.x >> 5);
    int lane = threadIdx.x & 31;
    if (node >= NN) return;
    const float4* __restrict__ x4 = (const float4*)X;
    const float4* __restrict__ ct4 = (const float4*)d_ctab;
    float4 sc0, sc1, sh0, sh1;
    if (APPLY) {
        sc0 = ((const float4*)d_scale)[lane];
        sc1 = ((const float4*)d_scale)[32 + lane];
        sh0 = ((const float4*)d_shift)[lane];
        sh1 = ((const float4*)d_shift)[32 + lane];
    }
    int i0 = node * 64 + lane;
    float4 a0 = x4[i0];
    float4 a1 = x4[i0 + 32];
    if (APPLY) { a0 = aff4(a0, sc0, sh0); a1 = aff4(a1, sc1, sh1); }
    acc4(a0, ct4[2048 + lane]);
    acc4(a1, ct4[2048 + 32 + lane]);
    int p0 = d_off[node], p1 = d_off[node + 1];
    for (int base = p0; base < p1; base += 32) {
        int cnt = p1 - base;
        if (cnt > 32) cnt = 32;
        int e = (lane < cnt) ? d_csr[base + lane] : 0;
        int j = 0;
        for (; j + 4 <= cnt; j += 4) {
            int e0 = __shfl_sync(0xffffffffu, e, j);
            int e1 = __shfl_sync(0xffffffffu, e, j + 1);
            int e2 = __shfl_sync(0xffffffffu, e, j + 2);
            int e3 = __shfl_sync(0xffffffffu, e, j + 3);
            int sA = (e0 & 0xFFFF) << 6, cA = (e0 >> 16) << 6;
            int sB = (e1 & 0xFFFF) << 6, cB = (e1 >> 16) << 6;
            int sC = (e2 & 0xFFFF) << 6, cC = (e2 >> 16) << 6;
            int sD = (e3 & 0xFFFF) << 6, cD = (e3 >> 16) << 6;
            float4 hA0 = x4[sA + lane], hB0 = x4[sB + lane];
            float4 hC0 = x4[sC + lane], hD0 = x4[sD + lane];
            float4 hA1 = x4[sA + 32 + lane], hB1 = x4[sB + 32 + lane];
            float4 hC1 = x4[sC + 32 + lane], hD1 = x4[sD + 32 + lane];
            if (APPLY) {
                hA0 = aff4(hA0, sc0, sh0); hB0 = aff4(hB0, sc0, sh0);
                hC0 = aff4(hC0, sc0, sh0); hD0 = aff4(hD0, sc0, sh0);
                hA1 = aff4(hA1, sc1, sh1); hB1 = aff4(hB1, sc1, sh1);
                hC1 = aff4(hC1, sc1, sh1); hD1 = aff4(hD1, sc1, sh1);
            }
            acc4(a0, hA0); acc4(a0, hB0); acc4(a0, hC0); acc4(a0, hD0);
            acc4(a1, hA1); acc4(a1, hB1); acc4(a1, hC1); acc4(a1, hD1);
            acc4(a0, ct4[cA + lane]); acc4(a0, ct4[cB + lane]);
            acc4(a0, ct4[cC + lane]); acc4(a0, ct4[cD + lane]);
            acc4(a1, ct4[cA + 32 + lane]); acc4(a1, ct4[cB + 32 + lane]);
            acc4(a1, ct4[cC + 32 + lane]); acc4(a1, ct4[cD + 32 + lane]);
        }
        for (; j < cnt; j++) {
            int e0 = __shfl_sync(0xffffffffu, e, j);
            int sA = (e0 & 0xFFFF) << 6, cA = (e0 >> 16) << 6;
            float4 hA0 = x4[sA + lane], hA1 = x4[sA + 32 + lane];
            if (APPLY) { hA0 = aff4(hA0, sc0, sh0); hA1 = aff4(hA1, sc1, sh1); }
            acc4(a0, hA0); acc4(a0, ct4[cA + lane]);
            acc4(a1, hA1); acc4(a1, ct4[cA + 32 + lane]);
        }
    }
    size_t ob = (size_t)node * 256 + lane * 4;
    store_hilo4(d_aggr_hi + ob, d_aggr_lo + ob, a0);
    store_hilo4(d_aggr_hi + ob + 128, d_aggr_lo + ob + 128, a1);
}

// ==================== HMMA GEMM with cp.async pipeline (128x128, 2 CTA/SM) ====================
// STATS=0: half hi/lo out (+relu).  STATS=1: fp32 out + per-rowblock column partials.
#define TILE_B 10240
#define GSMEM (2 * 4 * TILE_B)

template <int STATS>
__global__ __launch_bounds__(256, 2) void gemm_hmma(
    float* __restrict__ C, __half* __restrict__ Chi, __half* __restrict__ Clo,
    const __half* __restrict__ Ahi, const __half* __restrict__ Alo,
    const __half* __restrict__ Whi, const __half* __restrict__ Wlo,
    const float* __restrict__ bias, int nrows, int K, int M, int dorelu) {
    extern __shared__ char dynsmem[];
    const uint32_t sbase = smem_u32(dynsmem);

    const int tid = threadIdx.x;
    const int lane = tid & 31;
    const int wid = tid >> 5;
    const int warp_m = wid & 3;
    const int warp_n = wid >> 2;
    const int br = blockIdx.y * 128, bc = blockIdx.x * 128;

    float c[2][8][4];
#pragma unroll
    for (int i = 0; i < 2; i++)
#pragma unroll
        for (int j = 0; j < 8; j++)
#pragma unroll
            for (int k = 0; k < 4; k++) c[i][j][k] = 0.f;

    const int lrow = tid >> 1;
    const int lhalf = (tid & 1) * 16;
    const bool aval = (br + lrow) < nrows;
    const __half* gAh = (aval ? (Ahi + (size_t)(br + lrow) * K) : Ahi) + lhalf;
    const __half* gAl = (aval ? (Alo + (size_t)(br + lrow) * K) : Alo) + lhalf;
    const __half* gWh = Whi + (size_t)(bc + lrow) * K + lhalf;
    const __half* gWl = Wlo + (size_t)(bc + lrow) * K + lhalf;
    const uint32_t dst_off = lrow * 80 + (tid & 1) * 32;
    const int asz = aval ? 16 : 0;

    const int nchunk = K >> 5;

    {
        uint32_t d0 = sbase + dst_off;
        cp16(d0 + 0 * TILE_B, gAh, asz);       cp16(d0 + 0 * TILE_B + 16, gAh + 8, asz);
        cp16(d0 + 1 * TILE_B, gAl, asz);       cp16(d0 + 1 * TILE_B + 16, gAl + 8, asz);
        cp16(d0 + 2 * TILE_B, gWh, 16);        cp16(d0 + 2 * TILE_B + 16, gWh + 8, 16);
        cp16(d0 + 3 * TILE_B, gWl, 16);        cp16(d0 + 3 * TILE_B + 16, gWl + 8, 16);
        cp_commit();
    }

    const int lm_row = lane & 15;
    const int lm_kb = (lane & 16) ? 16 : 0;

    for (int kc = 0; kc < nchunk; kc++) {
        if (kc + 1 < nchunk) {
            uint32_t dn = sbase + ((kc + 1) & 1) * (4 * TILE_B) + dst_off;
            int go = (kc + 1) * 32;
            cp16(dn + 0 * TILE_B, gAh + go, asz); cp16(dn + 0 * TILE_B + 16, gAh + go + 8, asz);
            cp16(dn + 1 * TILE_B, gAl + go, asz); cp16(dn + 1 * TILE_B + 16, gAl + go + 8, asz);
            cp16(dn + 2 * TILE_B, gWh + go, 16);  cp16(dn + 2 * TILE_B + 16, gWh + go + 8, 16);
            cp16(dn + 3 * TILE_B, gWl + go, 16);  cp16(dn + 3 * TILE_B + 16, gWl + go + 8, 16);
            cp_commit();
            cp_wait<1>();
        } else {
            cp_wait<0>();
        }
        __syncthreads();

        const uint32_t bb = sbase + (kc & 1) * (4 * TILE_B);
#pragma unroll
        for (int kk = 0; kk < 2; kk++) {
            const int kbyte = kk * 32 + lm_kb;
            uint32_t ah[2][4], al[2][4];
#pragma unroll
            for (int mf = 0; mf < 2; mf++) {
                int row = warp_m * 32 + mf * 16 + lm_row;
                ldsm_x4(ah[mf], bb + 0 * TILE_B + row * 80 + kbyte);
                ldsm_x4(al[mf], bb + 1 * TILE_B + row * 80 + kbyte);
            }
#pragma unroll
            for (int nf4 = 0; nf4 < 4; nf4++) {
                int row = warp_n * 64 + nf4 * 16 + lm_row;
                uint32_t bh[4], bl[4];
                ldsm_x4(bh, bb + 2 * TILE_B + row * 80 + kbyte);
                ldsm_x4(bl, bb + 3 * TILE_B + row * 80 + kbyte);
                uint32_t bh0[2] = {bh[0], bh[2]}, bh1[2] = {bh[1], bh[3]};
                uint32_t bl0[2] = {bl[0], bl[2]}, bl1[2] = {bl[1], bl[3]};
#pragma unroll
                for (int mf = 0; mf < 2; mf++) {
                    mma_16816(c[mf][nf4 * 2 + 0], ah[mf], bh0);
                    mma_16816(c[mf][nf4 * 2 + 0], ah[mf], bl0);
                    mma_16816(c[mf][nf4 * 2 + 0], al[mf], bh0);
                    mma_16816(c[mf][nf4 * 2 + 1], ah[mf], bh1);
                    mma_16816(c[mf][nf4 * 2 + 1], ah[mf], bl1);
                    mma_16816(c[mf][nf4 * 2 + 1], al[mf], bh1);
                }
            }
        }
        __syncthreads();
    }

    // ---------------- epilogue ----------------
    const int erow = lane >> 2;
    const int ecol = (lane & 3) * 2;
#pragma unroll
    for (int mf = 0; mf < 2; mf++) {
#pragma unroll
        for (int half_ = 0; half_ < 2; half_++) {
            int r = br + warp_m * 32 + mf * 16 + erow + half_ * 8;
            bool ok = r < nrows;
#pragma unroll
            for (int nf = 0; nf < 8; nf++) {
                int col = bc + warp_n * 64 + nf * 8 + ecol;
                float v0 = 0.f, v1 = 0.f;
                if (ok) {
                    v0 = c[mf][nf][half_ * 2 + 0] + bias[col];
                    v1 = c[mf][nf][half_ * 2 + 1] + bias[col + 1];
                    if (dorelu) { v0 = fmaxf(v0, 0.f); v1 = fmaxf(v1, 0.f); }
                    if (STATS) {
                        *(float2*)(C + (size_t)r * M + col) = make_float2(v0, v1);
                    } else {
                        __half h0 = __float2half_rn(v0);
                        __half h1 = __float2half_rn(v1);
                        __half l0 = __float2half_rn(v0 - __half2float(h0));
                        __half l1 = __float2half_rn(v1 - __half2float(h1));
                        *(__half2*)(Chi + (size_t)r * M + col) = __halves2half2(h0, h1);
                        *(__half2*)(Clo + (size_t)r * M + col) = __halves2half2(l0, l1);
                    }
                }
                if (STATS) {
                    // stash final values back into the accumulator array (no extra regs)
                    c[mf][nf][half_ * 2 + 0] = v0;
                    c[mf][nf][half_ * 2 + 1] = v1;
                }
            }
        }
    }

    if (STATS) {
        // per-column row-sums: within thread (mf/half), across row-lanes (xor 4/8/16),
        // across warp_m via smem, written as per-rowblock partials (no atomics).
        float* sm = (float*)dynsmem;   // [4 warp_m][128 cols] sums, then +512 sumsq
#pragma unroll
        for (int nf = 0; nf < 8; nf++) {
#pragma unroll
            for (int j = 0; j < 2; j++) {
                float s = 0.f, q = 0.f;
#pragma unroll
                for (int mf = 0; mf < 2; mf++)
#pragma unroll
                    for (int h = 0; h < 2; h++) {
                        float v = c[mf][nf][h * 2 + j];
                        s += v;
                        q += v * v;
                    }
                s += __shfl_xor_sync(0xffffffffu, s, 4);
                s += __shfl_xor_sync(0xffffffffu, s, 8);
                s += __shfl_xor_sync(0xffffffffu, s, 16);
                q += __shfl_xor_sync(0xffffffffu, q, 4);
                q += __shfl_xor_sync(0xffffffffu, q, 8);
                q += __shfl_xor_sync(0xffffffffu, q, 16);
                if (lane < 4) {
                    int lc = warp_n * 64 + nf * 8 + lane * 2 + j;
                    sm[warp_m * 128 + lc] = s;
                    sm[512 + warp_m * 128 + lc] = q;
                }
            }
        }
        __syncthreads();
        if (tid < 128) {
            float ts = sm[tid] + sm[128 + tid] + sm[256 + tid] + sm[384 + tid];
            float tq = sm[512 + tid] + sm[512 + 128 + tid] + sm[512 + 256 + tid] + sm[512 + 384 + tid];
            d_gps[blockIdx.y * DD + bc + tid] = ts;
            d_gpq[blockIdx.y * DD + bc + tid] = tq;
        }
    }
}

// 1-block: fold the GYC row-block partials into BN affine coefficients
__global__ void prepare_from_parts(const float* __restrict__ g, const float* __restrict__ b,
                                   int nrows) {
    int d = threadIdx.x;
    double s = 0.0, q = 0.0;
    for (int p = 0; p < GYC; p++) {
        s += (double)d_gps[p * DD + d];
        q += (double)d_gpq[p * DD + d];
    }
    double m = s / (double)nrows;
    double var = q / (double)nrows - m * m;
    float inv = rsqrtf((float)var + EPSV);
    float sc = g[d] * inv;
    d_scale[d] = sc;
    d_shift[d] = b[d] - (float)m * sc;
}

// ==================== proj-head GEMM with per-block stats partials ====================
__global__ void gemm64s(float* __restrict__ C, const float* __restrict__ A,
                        const float* __restrict__ W, int nrows, int K, int M) {
    __shared__ float As[64][17];
    __shared__ float Ws[64][17];
    __shared__ float sred[16][68];
    int tid = threadIdx.x;
    int br = blockIdx.y * 64;
    int bc = blockIdx.x * 64;
    int ty = tid / 16, tx = tid % 16;
    int lr = tid / 4;
    int lc = (tid % 4) * 4;
    float acc[4][4];
#pragma unroll
    for (int i = 0; i < 4; i++)
#pragma unroll
        for (int j = 0; j < 4; j++) acc[i][j] = 0.f;
    for (int k0 = 0; k0 < K; k0 += 16) {
        {
            float4 v = *(const float4*)(A + (size_t)(br + lr) * K + k0 + lc);
            As[lr][lc + 0] = v.x; As[lr][lc + 1] = v.y;
            As[lr][lc + 2] = v.z; As[lr][lc + 3] = v.w;
        }
        {
            float4 v = *(const float4*)(W + (size_t)(bc + lr) * K + k0 + lc);
            Ws[lr][lc + 0] = v.x; Ws[lr][lc + 1] = v.y;
            Ws[lr][lc + 2] = v.z; Ws[lr][lc + 3] = v.w;
        }
        __syncthreads();
#pragma unroll
        for (int kk = 0; kk < 16; kk++) {
            float a[4], b[4];
#pragma unroll
            for (int i = 0; i < 4; i++) a[i] = As[ty * 4 + i][kk];
#pragma unroll
            for (int j = 0; j < 4; j++) b[j] = Ws[tx * 4 + j][kk];
#pragma unroll
            for (int i = 0; i < 4; i++)
#pragma unroll
                for (int j = 0; j < 4; j++) acc[i][j] = fmaf(a[i], b[j], acc[i][j]);
        }
        __syncthreads();
    }
#pragma unroll
    for (int i = 0; i < 4; i++) {
        int r = br + ty * 4 + i;
#pragma unroll
        for (int j = 0; j < 4; j++)
            C[(size_t)r * M + bc + tx * 4 + j] = acc[i][j];
    }
#pragma unroll
    for (int j = 0; j < 4; j++)
        sred[ty][tx * 4 + j] = acc[0][j] + acc[1][j] + acc[2][j] + acc[3][j];
    __syncthreads();
    if (tid < 64) {
        float s = 0.f;
#pragma unroll
        for (int y = 0; y < 16; y++) s += sred[y][tid];
        d_pp[blockIdx.y * DD + bc + tid] = s;
    }
    __syncthreads();
#pragma unroll
    for (int j = 0; j < 4; j++)
        sred[ty][tx * 4 + j] = acc[0][j] * acc[0][j] + acc[1][j] * acc[1][j]
                             + acc[2][j] * acc[2][j] + acc[3][j] * acc[3][j];
    __syncthreads();
    if (tid < 64) {
        float q = 0.f;
#pragma unroll
        for (int y = 0; y < 16; y++) q += sred[y][tid];
        d_pq[blockIdx.y * DD + bc + tid] = q;
    }
}

__global__ void bn_affine_proj(float* __restrict__ outp, const float* __restrict__ X,
                               const float* __restrict__ g, const float* __restrict__ b,
                               int dorelu) {
    int i = blockIdx.x, d = threadIdx.x;
    float s = d_pp[d] + d_pp[DD + d] + d_pp[2 * DD + d] + d_pp[3 * DD + d];
    float q = d_pq[d] + d_pq[DD + d] + d_pq[2 * DD + d] + d_pq[3 * DD + d];
    float m = s / (float)GG;
    float var = q / (float)GG - m * m;
    float inv = rsqrtf(var + EPSV);
    float sc = g[d] * inv;
    float sh = b[d] - m * sc;
    float v = fmaf(X[(size_t)i * DD + d], sc, sh);
    if (dorelu) v = fmaxf(v, 0.f);
    outp[(size_t)i * DD + d] = v;
}

// ==================== pooling (final BN affine + relu fused into the reduce) ====================
__global__ void gs_init_kernel() {
    int g = threadIdx.x + blockIdx.x * blockDim.x;
    if (g <= GG) d_gs[g] = NN;
}

__global__ void gs_min_kernel(const int* __restrict__ batch) {
    int i = blockIdx.x * blockDim.x + threadIdx.x;
    if (i < NN) atomicMin(&d_gs[batch[i]], i);
}

__global__ void gs_fix_kernel() {
    for (int g = GG - 1; g >= 0; g--)
        if (d_gs[g] > d_gs[g + 1]) d_gs[g] = d_gs[g + 1];
}

__global__ void pool_kernel() {
    int g = blockIdx.x, d = threadIdx.x;
    int s0 = d_gs[g], s1 = d_gs[g + 1];
    float sc = d_scale[d], sh = d_shift[d];
    float acc = 0.f;
    for (int i = s0; i < s1; i++)
        acc += fmaxf(fmaf(d_hh[(size_t)i * DD + d], sc, sh), 0.f);
    int c = s1 - s0;
    if (c < 1) c = 1;
    d_hg[(size_t)g * DD + d] = acc / (float)c;
}

// ==================== output MLP ====================
__global__ void out_kernel(float* __restrict__ outp,
                           const float* __restrict__ ow1, const float* __restrict__ ob1,
                           const float* __restrict__ ow2, const float* __restrict__ ob2) {
    int g = blockIdx.x;
    int t = threadIdx.x;
    __shared__ float sp[128];
    const float* row = d_hg + (size_t)g * DD;
    float acc = ob1[t];
    for (int k = 0; k < DD; k++) acc = fmaf(row[k], ow1[t * DD + k], acc);
    float v = (acc > 20.f) ? acc : log1pf(expf(acc));
    sp[t] = v;
    __syncthreads();
    if (t < 2) {
        float o = ob2[t];
        for (int k = 0; k < 128; k++) o = fmaf(sp[k], ow2[t * 128 + k], o);
        outp[g * 2 + t] = o;
    }
}

// ==================== launch ====================
extern "C" void kernel_launch(void* const* d_in, const int* in_sizes, int n_in,
                              void* d_out, int out_size) {
    const int* xf = (const int*)d_in[0];
    const int* ei = (const int*)d_in[1];
    const int* ea = (const int*)d_in[2];
    const int* batch = (const int*)d_in[3];
    const float* nt1 = (const float*)d_in[4];
    const float* nt2 = (const float*)d_in[5];
    const float* nt3 = (const float*)d_in[6];
    const float* nt4 = (const float*)d_in[7];
    const float* nt5 = (const float*)d_in[8];
    const float* nt6 = (const float*)d_in[9];
    const float* et1 = (const float*)d_in[10];
    const float* et2 = (const float*)d_in[11];
    const float* et3 = (const float*)d_in[12];
    const float* et4 = (const float*)d_in[13];
    const float* et5 = (const float*)d_in[14];
    const float* w1 = (const float*)d_in[15];
    const float* b1 = (const float*)d_in[16];
    const float* w2 = (const float*)d_in[17];
    const float* b2 = (const float*)d_in[18];
    const float* bng = (const float*)d_in[19];
    const float* bnb = (const float*)d_in[20];
    const float* pw = (const float*)d_in[21];
    const float* pg = (const float*)d_in[22];
    const float* pb = (const float*)d_in[23];
    const float* ow1 = (const float*)d_in[24];
    const float* ob1 = (const float*)d_in[25];
    const float* ow2 = (const float*)d_in[26];
    const float* ob2 = (const float*)d_in[27];
    float* outp = (float*)d_out;

    float *p_h, *p_hh, *p_hg, *p_hg2;
    __half *p_ahi, *p_alo, *p_hhi, *p_hlo, *p_w1hi, *p_w1lo, *p_w2hi, *p_w2lo;
    cudaGetSymbolAddress((void**)&p_h, d_h);
    cudaGetSymbolAddress((void**)&p_hh, d_hh);
    cudaGetSymbolAddress((void**)&p_hg, d_hg);
    cudaGetSymbolAddress((void**)&p_hg2, d_hg2);
    cudaGetSymbolAddress((void**)&p_ahi, d_aggr_hi);
    cudaGetSymbolAddress((void**)&p_alo, d_aggr_lo);
    cudaGetSymbolAddress((void**)&p_hhi, d_hid_hi);
    cudaGetSymbolAddress((void**)&p_hlo, d_hid_lo);
    cudaGetSymbolAddress((void**)&p_w1hi, d_w1hi);
    cudaGetSymbolAddress((void**)&p_w1lo, d_w1lo);
    cudaGetSymbolAddress((void**)&p_w2hi, d_w2hi);
    cudaGetSymbolAddress((void**)&p_w2lo, d_w2lo);

    cudaFuncSetAttribute(gemm_hmma<0>, cudaFuncAttributeMaxDynamicSharedMemorySize, GSMEM);
    cudaFuncSetAttribute(gemm_hmma<1>, cudaFuncAttributeMaxDynamicSharedMemorySize, GSMEM);

    embed_kernel<<<NN, DD>>>(xf, nt1, nt2, nt3, nt4, nt5, nt6);

    const int WN = LL * 2 * DD * DD;
    wconv_kernel<<<(WN + 255) / 256, 256>>>(w1, p_w1hi, p_w1lo, WN);
    wconv_kernel<<<(WN + 255) / 256, 256>>>(w2, p_w2hi, p_w2lo, WN);

    const int SBLK = (NN + 1023) / 1024;  // 20
    zero_deg_kernel<<<(NN + 255) / 256, 256>>>();
    count_kernel<<<(EE + 255) / 256, 256>>>(ei);
    scan1_kernel<<<SBLK, 1024>>>();
    scan2_kernel<<<1, 32>>>(SBLK);
    scan3_kernel<<<SBLK, 1024>>>();
    fill_kernel<<<(EE + 255) / 256, 256>>>(ei, ea);

    for (int l = 0; l < LL; l++) {
        ctab_kernel<<<33, DD>>>(l, et1, et2, et3, et4, et5);
        if (l == 0)
            spmm_kernel<0><<<NN / 8, 256>>>(p_h);
        else
            spmm_kernel<1><<<NN / 8, 256>>>(p_hh);
        gemm_hmma<0><<<dim3(4, GYC), 256, GSMEM>>>(
            nullptr, p_hhi, p_hlo, p_ahi, p_alo,
            p_w1hi + (size_t)l * 2 * DD * DD, p_w1lo + (size_t)l * 2 * DD * DD,
            b1 + (size_t)l * 2 * DD, NN, DD, 2 * DD, 1);
        gemm_hmma<1><<<dim3(2, GYC), 256, GSMEM>>>(
            p_hh, nullptr, nullptr, p_hhi, p_hlo,
            p_w2hi + (size_t)l * 2 * DD * DD, p_w2lo + (size_t)l * 2 * DD * DD,
            b2 + (size_t)l * DD, NN, 2 * DD, DD, 0);
        prepare_from_parts<<<1, DD>>>(bng + (size_t)l * DD, bnb + (size_t)l * DD, NN);
    }

    // pooling (applies layer-5 BN affine + relu inline)
    gs_init_kernel<<<2, 256>>>();
    gs_min_kernel<<<(NN + 255) / 256, 256>>>(batch);
    gs_fix_kernel<<<1, 1>>>();
    pool_kernel<<<GG, DD>>>();

    for (int i = 0; i < 3; i++) {
        gemm64s<<<dim3(4, 4), 256>>>(p_hg2, p_hg, pw + (size_t)i * DD * DD, GG, DD, DD);
        bn_affine_proj<<<GG, DD>>>(p_hg, p_hg2, pg + (size_t)i * DD, pb + (size_t)i * DD,
                                   (i < 2) ? 1 : 0);
    }

    out_kernel<<<GG, 128>>>(outp, ow1, ob1, ow2, ob2);
}

// round 13
// speedup vs baseline: 1.1799x; 1.1799x over previous
#include <cuda_runtime.h>
#include <cuda_fp16.h>
#include <math.h>
#include <stdint.h>

#define NN 20000
#define EE 320000
#define GG 256
#define DD 256
#define LL 5
#define EPSV 1e-5f

// ==================== device scratch ====================
__device__ float d_h[NN * DD];
__device__ float d_hh[NN * DD];
__device__ __half d_aggr_hi[NN * DD];
__device__ __half d_aggr_lo[NN * DD];
__device__ __half d_hid_hi[NN * 2 * DD];
__device__ __half d_hid_lo[NN * 2 * DD];
__device__ __half d_w1hi[LL * 2 * DD * DD];
__device__ __half d_w1lo[LL * 2 * DD * DD];
__device__ __half d_w2hi[LL * 2 * DD * DD];
__device__ __half d_w2lo[LL * 2 * DD * DD];
__device__ double d_colsum[DD];
__device__ double d_colsq[DD];
__device__ float d_scale[DD];
__device__ float d_shift[DD];
__device__ float d_hg[GG * DD];
__device__ float d_hg2[GG * DD];
__device__ float d_pp[4 * DD];    // proj-head col-sum partials
__device__ float d_pq[4 * DD];    // proj-head col-sumsq partials
__device__ float d_ctab[33 * DD];
__device__ int d_deg[NN];
__device__ int d_off[NN + 1];
__device__ int d_cur[NN];
__device__ int d_csr[EE];
__device__ int d_bsum[32];
__device__ int d_boff[32];
__device__ int d_lastblk;         // colstats last-block counter (self-resetting)

// ==================== PTX helpers ====================
__device__ __forceinline__ uint32_t smem_u32(const void* p) {
    uint32_t a;
    asm("{ .reg .u64 t; cvta.to.shared.u64 t, %1; cvt.u32.u64 %0, t; }" : "=r"(a) : "l"(p));
    return a;
}

__device__ __forceinline__ void ldsm_x4(uint32_t* r, uint32_t addr) {
    asm volatile("ldmatrix.sync.aligned.m8n8.x4.shared.b16 {%0,%1,%2,%3}, [%4];"
                 : "=r"(r[0]), "=r"(r[1]), "=r"(r[2]), "=r"(r[3]) : "r"(addr));
}

__device__ __forceinline__ void mma_16816(float* d, const uint32_t* a, const uint32_t* b) {
    asm volatile(
        "mma.sync.aligned.m16n8k16.row.col.f32.f16.f16.f32 "
        "{%0,%1,%2,%3}, {%4,%5,%6,%7}, {%8,%9}, {%0,%1,%2,%3};"
        : "+f"(d[0]), "+f"(d[1]), "+f"(d[2]), "+f"(d[3])
        : "r"(a[0]), "r"(a[1]), "r"(a[2]), "r"(a[3]), "r"(b[0]), "r"(b[1]));
}

__device__ __forceinline__ void cp16(uint32_t dst, const void* src, int srcsz) {
    asm volatile("cp.async.cg.shared.global [%0], [%1], 16, %2;"
                 :: "r"(dst), "l"(src), "r"(srcsz) : "memory");
}
__device__ __forceinline__ void cp_commit() {
    asm volatile("cp.async.commit_group;" ::: "memory");
}
template <int N>
__device__ __forceinline__ void cp_wait() {
    asm volatile("cp.async.wait_group %0;" :: "n"(N) : "memory");
}

__device__ __forceinline__ void acc4(float4& a, const float4 b) {
    a.x += b.x; a.y += b.y; a.z += b.z; a.w += b.w;
}
__device__ __forceinline__ float4 aff4(float4 x, const float4 sc, const float4 sh) {
    float4 r;
    r.x = fmaxf(fmaf(x.x, sc.x, sh.x), 0.f);
    r.y = fmaxf(fmaf(x.y, sc.y, sh.y), 0.f);
    r.z = fmaxf(fmaf(x.z, sc.z, sh.z), 0.f);
    r.w = fmaxf(fmaf(x.w, sc.w, sh.w), 0.f);
    return r;
}

// ==================== embeddings (+ deg zero fused) ====================
__global__ void embed_kernel(const int* __restrict__ xf,
                             const float* __restrict__ nt1, const float* __restrict__ nt2,
                             const float* __restrict__ nt3, const float* __restrict__ nt4,
                             const float* __restrict__ nt5, const float* __restrict__ nt6) {
    int i = blockIdx.x;
    int d = threadIdx.x;
    __shared__ int f[6];
    if (d < 6) f[d] = xf[i * 6 + d];
    if (d == 6) d_deg[i] = 0;   // fused CSR degree zeroing
    __syncthreads();
    d_h[i * DD + d] = nt1[f[0] * DD + d] + nt2[f[1] * DD + d] + nt3[f[2] * DD + d]
                    + nt4[f[3] * DD + d] + nt5[f[4] * DD + d] + nt6[f[5] * DD + d];
}

// ==================== weight split fp32 -> fp16 hi/lo (both tensors, one launch) ====================
__global__ void wconv_kernel(const float* __restrict__ w1, const float* __restrict__ w2,
                             __half* __restrict__ hi1, __half* __restrict__ lo1,
                             __half* __restrict__ hi2, __half* __restrict__ lo2, int n) {
    int i = blockIdx.x * blockDim.x + threadIdx.x;
    if (i < n) {
        float v = w1[i];
        __half h = __float2half_rn(v);
        hi1[i] = h;
        lo1[i] = __float2half_rn(v - __half2float(h));
    } else if (i < 2 * n) {
        int j = i - n;
        float v = w2[j];
        __half h = __float2half_rn(v);
        hi2[j] = h;
        lo2[j] = __float2half_rn(v - __half2float(h));
    }
}

// ==================== CSR build ====================
__global__ void count_kernel(const int* __restrict__ ei) {
    int e = blockIdx.x * blockDim.x + threadIdx.x;
    if (e >= EE) return;
    atomicAdd(&d_deg[ei[EE + e]], 1);
}

__global__ void scan1_kernel() {
    __shared__ int wsum[32];
    int tid = threadIdx.x;
    int lane = tid & 31, w = tid >> 5;
    int idx = blockIdx.x * 1024 + tid;
    int v = (idx < NN) ? d_deg[idx] : 0;
    int x = v;
#pragma unroll
    for (int o = 1; o < 32; o <<= 1) {
        int y = __shfl_up_sync(0xffffffffu, x, o);
        if (lane >= o) x += y;
    }
    if (lane == 31) wsum[w] = x;
    __syncthreads();
    if (w == 0) {
        int s = wsum[lane];
#pragma unroll
        for (int o = 1; o < 32; o <<= 1) {
            int y = __shfl_up_sync(0xffffffffu, s, o);
            if (lane >= o) s += y;
        }
        wsum[lane] = s;
    }
    __syncthreads();
    int incl = x + ((w > 0) ? wsum[w - 1] : 0);
    if (idx < NN) d_off[idx] = incl - v;
    if (tid == 1023) d_bsum[blockIdx.x] = incl;
}

__global__ void scan2_kernel(int nblk) {
    int lane = threadIdx.x;
    int v = (lane < nblk) ? d_bsum[lane] : 0;
    int x = v;
#pragma unroll
    for (int o = 1; o < 32; o <<= 1) {
        int y = __shfl_up_sync(0xffffffffu, x, o);
        if (lane >= o) x += y;
    }
    if (lane < nblk) d_boff[lane] = x - v;
}

__global__ void scan3_kernel() {
    int idx = blockIdx.x * 1024 + threadIdx.x;
    if (idx < NN) {
        int o = d_off[idx] + d_boff[blockIdx.x];
        d_off[idx] = o;
        d_cur[idx] = o;
    }
    if (idx == 0) d_off[NN] = EE;
}

__global__ void fill_kernel(const int* __restrict__ ei, const int* __restrict__ ea) {
    int e = blockIdx.x * blockDim.x + threadIdx.x;
    if (e >= EE) return;
    int src = ei[e];
    int dst = ei[EE + e];
    int combo = (ea[e * 5 + 0] & 1) | ((ea[e * 5 + 1] & 1) << 1) | ((ea[e * 5 + 2] & 1) << 2)
              | ((ea[e * 5 + 3] & 1) << 3) | ((ea[e * 5 + 4] & 1) << 4);
    int pos = atomicAdd(&d_cur[dst], 1);
    d_csr[pos] = src | (combo << 16);
}

// ==================== per-layer combo table (+ stats zero) ====================
__global__ void ctab_kernel(int l,
                            const float* __restrict__ et1, const float* __restrict__ et2,
                            const float* __restrict__ et3, const float* __restrict__ et4,
                            const float* __restrict__ et5) {
    int c = blockIdx.x;
    int d = threadIdx.x;
    if (c == 0) { d_colsum[d] = 0.0; d_colsq[d] = 0.0; }
    float v;
    if (c == 32) {
        v = et1[(l * 5 + 4) * DD + d] + et2[(l * 4 + 0) * DD + d] + et3[(l * 2 + 0) * DD + d]
          + et4[(l * 2 + 0) * DD + d] + et5[(l * 2 + 0) * DD + d];
    } else {
        v = et1[(l * 5 + (c & 1)) * DD + d] + et2[(l * 4 + ((c >> 1) & 1)) * DD + d]
          + et3[(l * 2 + ((c >> 2) & 1)) * DD + d] + et4[(l * 2 + ((c >> 3) & 1)) * DD + d]
          + et5[(l * 2 + ((c >> 4) & 1)) * DD + d];
    }
    d_ctab[c * DD + d] = v;
}

// ==================== SpMM: warp per node, 4-edge unroll, fused BN affine ====================
__device__ __forceinline__ void store_hilo4(__half* hi, __half* lo, float4 v) {
    __half h0 = __float2half_rn(v.x), h1 = __float2half_rn(v.y);
    __half h2 = __float2half_rn(v.z), h3 = __float2half_rn(v.w);
    ((__half2*)hi)[0] = __halves2half2(h0, h1);
    ((__half2*)hi)[1] = __halves2half2(h2, h3);
    __half l0 = __float2half_rn(v.x - __half2float(h0));
    __half l1 = __float2half_rn(v.y - __half2float(h1));
    __half l2 = __float2half_rn(v.z - __half2float(h2));
    __half l3 = __float2half_rn(v.w - __half2float(h3));
    ((__half2*)lo)[0] = __halves2half2(l0, l1);
    ((__half2*)lo)[1] = __halves2half2(l2, l3);
}

// APPLY=0: X already activated (layer 0).  APPLY=1: X raw hh; apply relu(x*sc+sh) on the fly.
template <int APPLY>
__global__ __launch_bounds__(256) void spmm_kernel(const float* __restrict__ X) {
    int node = (blockIdx.x << 3) + (threadIdx.x >> 5);
    int lane = threadIdx.x & 31;
    if (node >= NN) return;
    const float4* __restrict__ x4 = (const float4*)X;
    const float4* __restrict__ ct4 = (const float4*)d_ctab;
    float4 sc0, sc1, sh0, sh1;
    if (APPLY) {
        sc0 = ((const float4*)d_scale)[lane];
        sc1 = ((const float4*)d_scale)[32 + lane];
        sh0 = ((const float4*)d_shift)[lane];
        sh1 = ((const float4*)d_shift)[32 + lane];
    }
    int i0 = node * 64 + lane;
    float4 a0 = x4[i0];
    float4 a1 = x4[i0 + 32];
    if (APPLY) { a0 = aff4(a0, sc0, sh0); a1 = aff4(a1, sc1, sh1); }
    acc4(a0, ct4[2048 + lane]);
    acc4(a1, ct4[2048 + 32 + lane]);
    int p0 = d_off[node], p1 = d_off[node + 1];
    for (int base = p0; base < p1; base += 32) {
        int cnt = p1 - base;
        if (cnt > 32) cnt = 32;
        int e = (lane < cnt) ? d_csr[base + lane] : 0;
        int j = 0;
        for (; j + 4 <= cnt; j += 4) {
            int e0 = __shfl_sync(0xffffffffu, e, j);
            int e1 = __shfl_sync(0xffffffffu, e, j + 1);
            int e2 = __shfl_sync(0xffffffffu, e, j + 2);
            int e3 = __shfl_sync(0xffffffffu, e, j + 3);
            int sA = (e0 & 0xFFFF) << 6, cA = (e0 >> 16) << 6;
            int sB = (e1 & 0xFFFF) << 6, cB = (e1 >> 16) << 6;
            int sC = (e2 & 0xFFFF) << 6, cC = (e2 >> 16) << 6;
            int sD = (e3 & 0xFFFF) << 6, cD = (e3 >> 16) << 6;
            float4 hA0 = x4[sA + lane], hB0 = x4[sB + lane];
            float4 hC0 = x4[sC + lane], hD0 = x4[sD + lane];
            float4 hA1 = x4[sA + 32 + lane], hB1 = x4[sB + 32 + lane];
            float4 hC1 = x4[sC + 32 + lane], hD1 = x4[sD + 32 + lane];
            if (APPLY) {
                hA0 = aff4(hA0, sc0, sh0); hB0 = aff4(hB0, sc0, sh0);
                hC0 = aff4(hC0, sc0, sh0); hD0 = aff4(hD0, sc0, sh0);
                hA1 = aff4(hA1, sc1, sh1); hB1 = aff4(hB1, sc1, sh1);
                hC1 = aff4(hC1, sc1, sh1); hD1 = aff4(hD1, sc1, sh1);
            }
            acc4(a0, hA0); acc4(a0, hB0); acc4(a0, hC0); acc4(a0, hD0);
            acc4(a1, hA1); acc4(a1, hB1); acc4(a1, hC1); acc4(a1, hD1);
            acc4(a0, ct4[cA + lane]); acc4(a0, ct4[cB + lane]);
            acc4(a0, ct4[cC + lane]); acc4(a0, ct4[cD + lane]);
            acc4(a1, ct4[cA + 32 + lane]); acc4(a1, ct4[cB + 32 + lane]);
            acc4(a1, ct4[cC + 32 + lane]); acc4(a1, ct4[cD + 32 + lane]);
        }
        for (; j < cnt; j++) {
            int e0 = __shfl_sync(0xffffffffu, e, j);
            int sA = (e0 & 0xFFFF) << 6, cA = (e0 >> 16) << 6;
            float4 hA0 = x4[sA + lane], hA1 = x4[sA + 32 + lane];
            if (APPLY) { hA0 = aff4(hA0, sc0, sh0); hA1 = aff4(hA1, sc1, sh1); }
            acc4(a0, hA0); acc4(a0, ct4[cA + lane]);
            acc4(a1, hA1); acc4(a1, ct4[cA + 32 + lane]);
        }
    }
    size_t ob = (size_t)node * 256 + lane * 4;
    store_hilo4(d_aggr_hi + ob, d_aggr_lo + ob, a0);
    store_hilo4(d_aggr_hi + ob + 128, d_aggr_lo + ob + 128, a1);
}

// ==================== HMMA GEMM with cp.async pipeline (128x128, 2 CTA/SM) ====================
#define TILE_B 10240
#define GSMEM (2 * 4 * TILE_B)

template <int OUTF32>
__global__ __launch_bounds__(256, 2) void gemm_hmma(
    float* __restrict__ C, __half* __restrict__ Chi, __half* __restrict__ Clo,
    const __half* __restrict__ Ahi, const __half* __restrict__ Alo,
    const __half* __restrict__ Whi, const __half* __restrict__ Wlo,
    const float* __restrict__ bias, int nrows, int K, int M, int dorelu) {
    extern __shared__ char dynsmem[];
    const uint32_t sbase = smem_u32(dynsmem);

    const int tid = threadIdx.x;
    const int lane = tid & 31;
    const int wid = tid >> 5;
    const int warp_m = wid & 3;
    const int warp_n = wid >> 2;
    const int br = blockIdx.y * 128, bc = blockIdx.x * 128;

    float c[2][8][4];
#pragma unroll
    for (int i = 0; i < 2; i++)
#pragma unroll
        for (int j = 0; j < 8; j++)
#pragma unroll
            for (int k = 0; k < 4; k++) c[i][j][k] = 0.f;

    const int lrow = tid >> 1;
    const int lhalf = (tid & 1) * 16;
    const bool aval = (br + lrow) < nrows;
    const __half* gAh = (aval ? (Ahi + (size_t)(br + lrow) * K) : Ahi) + lhalf;
    const __half* gAl = (aval ? (Alo + (size_t)(br + lrow) * K) : Alo) + lhalf;
    const __half* gWh = Whi + (size_t)(bc + lrow) * K + lhalf;
    const __half* gWl = Wlo + (size_t)(bc + lrow) * K + lhalf;
    const uint32_t dst_off = lrow * 80 + (tid & 1) * 32;
    const int asz = aval ? 16 : 0;

    const int nchunk = K >> 5;

    {
        uint32_t d0 = sbase + dst_off;
        cp16(d0 + 0 * TILE_B, gAh, asz);       cp16(d0 + 0 * TILE_B + 16, gAh + 8, asz);
        cp16(d0 + 1 * TILE_B, gAl, asz);       cp16(d0 + 1 * TILE_B + 16, gAl + 8, asz);
        cp16(d0 + 2 * TILE_B, gWh, 16);        cp16(d0 + 2 * TILE_B + 16, gWh + 8, 16);
        cp16(d0 + 3 * TILE_B, gWl, 16);        cp16(d0 + 3 * TILE_B + 16, gWl + 8, 16);
        cp_commit();
    }

    const int lm_row = lane & 15;
    const int lm_kb = (lane & 16) ? 16 : 0;

    for (int kc = 0; kc < nchunk; kc++) {
        if (kc + 1 < nchunk) {
            uint32_t dn = sbase + ((kc + 1) & 1) * (4 * TILE_B) + dst_off;
            int go = (kc + 1) * 32;
            cp16(dn + 0 * TILE_B, gAh + go, asz); cp16(dn + 0 * TILE_B + 16, gAh + go + 8, asz);
            cp16(dn + 1 * TILE_B, gAl + go, asz); cp16(dn + 1 * TILE_B + 16, gAl + go + 8, asz);
            cp16(dn + 2 * TILE_B, gWh + go, 16);  cp16(dn + 2 * TILE_B + 16, gWh + go + 8, 16);
            cp16(dn + 3 * TILE_B, gWl + go, 16);  cp16(dn + 3 * TILE_B + 16, gWl + go + 8, 16);
            cp_commit();
            cp_wait<1>();
        } else {
            cp_wait<0>();
        }
        __syncthreads();

        const uint32_t bb = sbase + (kc & 1) * (4 * TILE_B);
#pragma unroll
        for (int kk = 0; kk < 2; kk++) {
            const int kbyte = kk * 32 + lm_kb;
            uint32_t ah[2][4], al[2][4];
#pragma unroll
            for (int mf = 0; mf < 2; mf++) {
                int row = warp_m * 32 + mf * 16 + lm_row;
                ldsm_x4(ah[mf], bb + 0 * TILE_B + row * 80 + kbyte);
                ldsm_x4(al[mf], bb + 1 * TILE_B + row * 80 + kbyte);
            }
#pragma unroll
            for (int nf4 = 0; nf4 < 4; nf4++) {
                int row = warp_n * 64 + nf4 * 16 + lm_row;
                uint32_t bh[4], bl[4];
                ldsm_x4(bh, bb + 2 * TILE_B + row * 80 + kbyte);
                ldsm_x4(bl, bb + 3 * TILE_B + row * 80 + kbyte);
                uint32_t bh0[2] = {bh[0], bh[2]}, bh1[2] = {bh[1], bh[3]};
                uint32_t bl0[2] = {bl[0], bl[2]}, bl1[2] = {bl[1], bl[3]};
#pragma unroll
                for (int mf = 0; mf < 2; mf++) {
                    mma_16816(c[mf][nf4 * 2 + 0], ah[mf], bh0);
                    mma_16816(c[mf][nf4 * 2 + 0], ah[mf], bl0);
                    mma_16816(c[mf][nf4 * 2 + 0], al[mf], bh0);
                    mma_16816(c[mf][nf4 * 2 + 1], ah[mf], bh1);
                    mma_16816(c[mf][nf4 * 2 + 1], ah[mf], bl1);
                    mma_16816(c[mf][nf4 * 2 + 1], al[mf], bh1);
                }
            }
        }
        __syncthreads();
    }

    const int erow = lane >> 2;
    const int ecol = (lane & 3) * 2;
#pragma unroll
    for (int mf = 0; mf < 2; mf++) {
#pragma unroll
        for (int half_ = 0; half_ < 2; half_++) {
            int r = br + warp_m * 32 + mf * 16 + erow + half_ * 8;
            bool ok = r < nrows;
            if (!ok) continue;
#pragma unroll
            for (int nf = 0; nf < 8; nf++) {
                int col = bc + warp_n * 64 + nf * 8 + ecol;
                float v0 = c[mf][nf][half_ * 2 + 0] + bias[col];
                float v1 = c[mf][nf][half_ * 2 + 1] + bias[col + 1];
                if (dorelu) { v0 = fmaxf(v0, 0.f); v1 = fmaxf(v1, 0.f); }
                if (OUTF32) {
                    *(float2*)(C + (size_t)r * M + col) = make_float2(v0, v1);
                } else {
                    __half h0 = __float2half_rn(v0);
                    __half h1 = __float2half_rn(v1);
                    __half l0 = __float2half_rn(v0 - __half2float(h0));
                    __half l1 = __float2half_rn(v1 - __half2float(h1));
                    *(__half2*)(Chi + (size_t)r * M + col) = __halves2half2(h0, h1);
                    *(__half2*)(Clo + (size_t)r * M + col) = __halves2half2(l0, l1);
                }
            }
        }
    }
}

// ==================== proj-head GEMM with per-block stats partials ====================
__global__ void gemm64s(float* __restrict__ C, const float* __restrict__ A,
                        const float* __restrict__ W, int nrows, int K, int M) {
    __shared__ float As[64][17];
    __shared__ float Ws[64][17];
    __shared__ float sred[16][68];
    int tid = threadIdx.x;
    int br = blockIdx.y * 64;
    int bc = blockIdx.x * 64;
    int ty = tid / 16, tx = tid % 16;
    int lr = tid / 4;
    int lc = (tid % 4) * 4;
    float acc[4][4];
#pragma unroll
    for (int i = 0; i < 4; i++)
#pragma unroll
        for (int j = 0; j < 4; j++) acc[i][j] = 0.f;
    for (int k0 = 0; k0 < K; k0 += 16) {
        {
            float4 v = *(const float4*)(A + (size_t)(br + lr) * K + k0 + lc);
            As[lr][lc + 0] = v.x; As[lr][lc + 1] = v.y;
            As[lr][lc + 2] = v.z; As[lr][lc + 3] = v.w;
        }
        {
            float4 v = *(const float4*)(W + (size_t)(bc + lr) * K + k0 + lc);
            Ws[lr][lc + 0] = v.x; Ws[lr][lc + 1] = v.y;
            Ws[lr][lc + 2] = v.z; Ws[lr][lc + 3] = v.w;
        }
        __syncthreads();
#pragma unroll
        for (int kk = 0; kk < 16; kk++) {
            float a[4], b[4];
#pragma unroll
            for (int i = 0; i < 4; i++) a[i] = As[ty * 4 + i][kk];
#pragma unroll
            for (int j = 0; j < 4; j++) b[j] = Ws[tx * 4 + j][kk];
#pragma unroll
            for (int i = 0; i < 4; i++)
#pragma unroll
                for (int j = 0; j < 4; j++) acc[i][j] = fmaf(a[i], b[j], acc[i][j]);
        }
        __syncthreads();
    }
#pragma unroll
    for (int i = 0; i < 4; i++) {
        int r = br + ty * 4 + i;
#pragma unroll
        for (int j = 0; j < 4; j++)
            C[(size_t)r * M + bc + tx * 4 + j] = acc[i][j];
    }
#pragma unroll
    for (int j = 0; j < 4; j++)
        sred[ty][tx * 4 + j] = acc[0][j] + acc[1][j] + acc[2][j] + acc[3][j];
    __syncthreads();
    if (tid < 64) {
        float s = 0.f;
#pragma unroll
        for (int y = 0; y < 16; y++) s += sred[y][tid];
        d_pp[blockIdx.y * DD + bc + tid] = s;
    }
    __syncthreads();
#pragma unroll
    for (int j = 0; j < 4; j++)
        sred[ty][tx * 4 + j] = acc[0][j] * acc[0][j] + acc[1][j] * acc[1][j]
                             + acc[2][j] * acc[2][j] + acc[3][j] * acc[3][j];
    __syncthreads();
    if (tid < 64) {
        float q = 0.f;
#pragma unroll
        for (int y = 0; y < 16; y++) q += sred[y][tid];
        d_pq[blockIdx.y * DD + bc + tid] = q;
    }
}

__global__ void bn_affine_proj(float* __restrict__ outp, const float* __restrict__ X,
                               const float* __restrict__ g, const float* __restrict__ b,
                               int dorelu) {
    int i = blockIdx.x, d = threadIdx.x;
    float s = d_pp[d] + d_pp[DD + d] + d_pp[2 * DD + d] + d_pp[3 * DD + d];
    float q = d_pq[d] + d_pq[DD + d] + d_pq[2 * DD + d] + d_pq[3 * DD + d];
    float m = s / (float)GG;
    float var = q / (float)GG - m * m;
    float inv = rsqrtf(var + EPSV);
    float sc = g[d] * inv;
    float sh = b[d] - m * sc;
    float v = fmaf(X[(size_t)i * DD + d], sc, sh);
    if (dorelu) v = fmaxf(v, 0.f);
    outp[(size_t)i * DD + d] = v;
}

// ==================== BN (main loop): colstats + fused last-block prepare ====================
__global__ void colstats_fused(const float* __restrict__ X, int nrows,
                               const float* __restrict__ g, const float* __restrict__ b) {
    int t = threadIdx.x;
    int r0 = blockIdx.x * 64;
    int rend = min(r0 + 64, nrows);
    float s = 0.f, ss = 0.f;
    for (int r = r0; r < rend; r++) {
        float v = X[(size_t)r * DD + t];
        s += v;
        ss += v * v;
    }
    atomicAdd(&d_colsum[t], (double)s);
    atomicAdd(&d_colsq[t], (double)ss);
    __threadfence();
    __shared__ int isLast;
    if (t == 0) isLast = (atomicAdd(&d_lastblk, 1) == (int)gridDim.x - 1);
    __syncthreads();
    if (isLast) {
        if (t == 0) d_lastblk = 0;  // self-reset for next launch/replay
        double m = d_colsum[t] / (double)nrows;
        double var = d_colsq[t] / (double)nrows - m * m;
        float inv = rsqrtf((float)var + EPSV);
        float sc = g[t] * inv;
        d_scale[t] = sc;
        d_shift[t] = b[t] - (float)m * sc;
    }
}

// ==================== pooling (binary-search boundaries + fused BN affine/relu) ====================
__global__ void pool_kernel(const int* __restrict__ batch) {
    int g = blockIdx.x, d = threadIdx.x;
    __shared__ int sb[2];
    if (d < 2) {
        int target = g + d;
        int lo = 0, hi = NN;
        while (lo < hi) {
            int mid = (lo + hi) >> 1;
            if (batch[mid] < target) lo = mid + 1; else hi = mid;
        }
        sb[d] = lo;
    }
    __syncthreads();
    int s0 = sb[0], s1 = sb[1];
    float sc = d_scale[d], sh = d_shift[d];
    float acc = 0.f;
    for (int i = s0; i < s1; i++)
        acc += fmaxf(fmaf(d_hh[(size_t)i * DD + d], sc, sh), 0.f);
    int c = s1 - s0;
    if (c < 1) c = 1;
    d_hg[(size_t)g * DD + d] = acc / (float)c;
}

// ==================== output MLP ====================
__global__ void out_kernel(float* __restrict__ outp,
                           const float* __restrict__ ow1, const float* __restrict__ ob1,
                           const float* __restrict__ ow2, const float* __restrict__ ob2) {
    int g = blockIdx.x;
    int t = threadIdx.x;
    __shared__ float sp[128];
    const float* row = d_hg + (size_t)g * DD;
    float acc = ob1[t];
    for (int k = 0; k < DD; k++) acc = fmaf(row[k], ow1[t * DD + k], acc);
    float v = (acc > 20.f) ? acc : log1pf(expf(acc));
    sp[t] = v;
    __syncthreads();
    if (t < 2) {
        float o = ob2[t];
        for (int k = 0; k < 128; k++) o = fmaf(sp[k], ow2[t * 128 + k], o);
        outp[g * 2 + t] = o;
    }
}

// ==================== launch ====================
extern "C" void kernel_launch(void* const* d_in, const int* in_sizes, int n_in,
                              void* d_out, int out_size) {
    const int* xf = (const int*)d_in[0];
    const int* ei = (const int*)d_in[1];
    const int* ea = (const int*)d_in[2];
    const int* batch = (const int*)d_in[3];
    const float* nt1 = (const float*)d_in[4];
    const float* nt2 = (const float*)d_in[5];
    const float* nt3 = (const float*)d_in[6];
    const float* nt4 = (const float*)d_in[7];
    const float* nt5 = (const float*)d_in[8];
    const float* nt6 = (const float*)d_in[9];
    const float* et1 = (const float*)d_in[10];
    const float* et2 = (const float*)d_in[11];
    const float* et3 = (const float*)d_in[12];
    const float* et4 = (const float*)d_in[13];
    const float* et5 = (const float*)d_in[14];
    const float* w1 = (const float*)d_in[15];
    const float* b1 = (const float*)d_in[16];
    const float* w2 = (const float*)d_in[17];
    const float* b2 = (const float*)d_in[18];
    const float* bng = (const float*)d_in[19];
    const float* bnb = (const float*)d_in[20];
    const float* pw = (const float*)d_in[21];
    const float* pg = (const float*)d_in[22];
    const float* pb = (const float*)d_in[23];
    const float* ow1 = (const float*)d_in[24];
    const float* ob1 = (const float*)d_in[25];
    const float* ow2 = (const float*)d_in[26];
    const float* ob2 = (const float*)d_in[27];
    float* outp = (float*)d_out;

    float *p_h, *p_hh, *p_hg, *p_hg2;
    __half *p_ahi, *p_alo, *p_hhi, *p_hlo, *p_w1hi, *p_w1lo, *p_w2hi, *p_w2lo;
    cudaGetSymbolAddress((void**)&p_h, d_h);
    cudaGetSymbolAddress((void**)&p_hh, d_hh);
    cudaGetSymbolAddress((void**)&p_hg, d_hg);
    cudaGetSymbolAddress((void**)&p_hg2, d_hg2);
    cudaGetSymbolAddress((void**)&p_ahi, d_aggr_hi);
    cudaGetSymbolAddress((void**)&p_alo, d_aggr_lo);
    cudaGetSymbolAddress((void**)&p_hhi, d_hid_hi);
    cudaGetSymbolAddress((void**)&p_hlo, d_hid_lo);
    cudaGetSymbolAddress((void**)&p_w1hi, d_w1hi);
    cudaGetSymbolAddress((void**)&p_w1lo, d_w1lo);
    cudaGetSymbolAddress((void**)&p_w2hi, d_w2hi);
    cudaGetSymbolAddress((void**)&p_w2lo, d_w2lo);

    cudaFuncSetAttribute(gemm_hmma<0>, cudaFuncAttributeMaxDynamicSharedMemorySize, GSMEM);
    cudaFuncSetAttribute(gemm_hmma<1>, cudaFuncAttributeMaxDynamicSharedMemorySize, GSMEM);

    embed_kernel<<<NN, DD>>>(xf, nt1, nt2, nt3, nt4, nt5, nt6);

    const int WN = LL * 2 * DD * DD;
    wconv_kernel<<<(2 * WN + 255) / 256, 256>>>(w1, w2, p_w1hi, p_w1lo, p_w2hi, p_w2lo, WN);

    const int SBLK = (NN + 1023) / 1024;  // 20
    count_kernel<<<(EE + 255) / 256, 256>>>(ei);
    scan1_kernel<<<SBLK, 1024>>>();
    scan2_kernel<<<1, 32>>>(SBLK);
    scan3_kernel<<<SBLK, 1024>>>();
    fill_kernel<<<(EE + 255) / 256, 256>>>(ei, ea);

    const int GY = (NN + 127) / 128;  // 157
    for (int l = 0; l < LL; l++) {
        ctab_kernel<<<33, DD>>>(l, et1, et2, et3, et4, et5);
        if (l == 0)
            spmm_kernel<0><<<NN / 8, 256>>>(p_h);
        else
            spmm_kernel<1><<<NN / 8, 256>>>(p_hh);
        gemm_hmma<0><<<dim3(4, GY), 256, GSMEM>>>(
            nullptr, p_hhi, p_hlo, p_ahi, p_alo,
            p_w1hi + (size_t)l * 2 * DD * DD, p_w1lo + (size_t)l * 2 * DD * DD,
            b1 + (size_t)l * 2 * DD, NN, DD, 2 * DD, 1);
        gemm_hmma<1><<<dim3(2, GY), 256, GSMEM>>>(
            p_hh, nullptr, nullptr, p_hhi, p_hlo,
            p_w2hi + (size_t)l * 2 * DD * DD, p_w2lo + (size_t)l * 2 * DD * DD,
            b2 + (size_t)l * DD, NN, 2 * DD, DD, 0);
        colstats_fused<<<(NN + 63) / 64, DD>>>(p_hh, NN,
                                               bng + (size_t)l * DD, bnb + (size_t)l * DD);
    }

    // pooling (applies layer-5 BN affine + relu inline; boundaries via binary search)
    pool_kernel<<<GG, DD>>>(batch);

    for (int i = 0; i < 3; i++) {
        gemm64s<<<dim3(4, 4), 256>>>(p_hg2, p_hg, pw + (size_t)i * DD * DD, GG, DD, DD);
        bn_affine_proj<<<GG, DD>>>(p_hg, p_hg2, pg + (size_t)i * DD, pb + (size_t)i * DD,
                                   (i < 2) ? 1 : 0);
    }

    out_kernel<<<GG, 128>>>(outp, ow1, ob1, ow2, ob2);
}

// round 14
// speedup vs baseline: 1.1822x; 1.0020x over previous
#include <cuda_runtime.h>
#include <cuda_fp16.h>
#include <math.h>
#include <stdint.h>

#define NN 20000
#define EE 320000
#define GG 256
#define DD 256
#define LL 5
#define EPSV 1e-5f

// ==================== device scratch ====================
__device__ float d_h[NN * DD];
__device__ float d_hh[NN * DD];
__device__ __half d_aggr_hi[NN * DD];
__device__ __half d_aggr_lo[NN * DD];
__device__ __half d_hid_hi[NN * 2 * DD];
__device__ __half d_hid_lo[NN * 2 * DD];
__device__ __half d_w1hi[LL * 2 * DD * DD];
__device__ __half d_w1lo[LL * 2 * DD * DD];
__device__ __half d_w2hi[LL * 2 * DD * DD];
__device__ __half d_w2lo[LL * 2 * DD * DD];
__device__ double d_colsum[DD];
__device__ double d_colsq[DD];
__device__ float d_scale[DD];
__device__ float d_shift[DD];
__device__ float d_hg[GG * DD];
__device__ float d_hg2[GG * DD];
__device__ float d_pp[4 * DD];    // proj-head col-sum partials
__device__ float d_pq[4 * DD];    // proj-head col-sumsq partials
__device__ float d_ctab[LL * 33 * DD];   // all layers precomputed
__device__ int d_deg[NN];
__device__ int d_off[NN + 1];
__device__ int d_cur[NN];
__device__ int d_csr[EE];
__device__ int d_bsum[32];
__device__ int d_boff[32];
__device__ int d_lastblk;         // colstats last-block counter (self-resetting)

// ==================== PTX helpers ====================
__device__ __forceinline__ uint32_t smem_u32(const void* p) {
    uint32_t a;
    asm("{ .reg .u64 t; cvta.to.shared.u64 t, %1; cvt.u32.u64 %0, t; }" : "=r"(a) : "l"(p));
    return a;
}

__device__ __forceinline__ void ldsm_x4(uint32_t* r, uint32_t addr) {
    asm volatile("ldmatrix.sync.aligned.m8n8.x4.shared.b16 {%0,%1,%2,%3}, [%4];"
                 : "=r"(r[0]), "=r"(r[1]), "=r"(r[2]), "=r"(r[3]) : "r"(addr));
}

__device__ __forceinline__ void mma_16816(float* d, const uint32_t* a, const uint32_t* b) {
    asm volatile(
        "mma.sync.aligned.m16n8k16.row.col.f32.f16.f16.f32 "
        "{%0,%1,%2,%3}, {%4,%5,%6,%7}, {%8,%9}, {%0,%1,%2,%3};"
        : "+f"(d[0]), "+f"(d[1]), "+f"(d[2]), "+f"(d[3])
        : "r"(a[0]), "r"(a[1]), "r"(a[2]), "r"(a[3]), "r"(b[0]), "r"(b[1]));
}

__device__ __forceinline__ void cp16(uint32_t dst, const void* src, int srcsz) {
    asm volatile("cp.async.cg.shared.global [%0], [%1], 16, %2;"
                 :: "r"(dst), "l"(src), "r"(srcsz) : "memory");
}
__device__ __forceinline__ void cp_commit() {
    asm volatile("cp.async.commit_group;" ::: "memory");
}
template <int N>
__device__ __forceinline__ void cp_wait() {
    asm volatile("cp.async.wait_group %0;" :: "n"(N) : "memory");
}

__device__ __forceinline__ void acc4(float4& a, const float4 b) {
    a.x += b.x; a.y += b.y; a.z += b.z; a.w += b.w;
}
__device__ __forceinline__ float4 aff4(float4 x, const float4 sc, const float4 sh) {
    float4 r;
    r.x = fmaxf(fmaf(x.x, sc.x, sh.x), 0.f);
    r.y = fmaxf(fmaf(x.y, sc.y, sh.y), 0.f);
    r.z = fmaxf(fmaf(x.z, sc.z, sh.z), 0.f);
    r.w = fmaxf(fmaf(x.w, sc.w, sh.w), 0.f);
    return r;
}

// ==================== embeddings (+ deg zero fused) ====================
__global__ void embed_kernel(const int* __restrict__ xf,
                             const float* __restrict__ nt1, const float* __restrict__ nt2,
                             const float* __restrict__ nt3, const float* __restrict__ nt4,
                             const float* __restrict__ nt5, const float* __restrict__ nt6) {
    int i = blockIdx.x;
    int d = threadIdx.x;
    __shared__ int f[6];
    if (d < 6) f[d] = xf[i * 6 + d];
    if (d == 6) d_deg[i] = 0;
    __syncthreads();
    d_h[i * DD + d] = nt1[f[0] * DD + d] + nt2[f[1] * DD + d] + nt3[f[2] * DD + d]
                    + nt4[f[3] * DD + d] + nt5[f[4] * DD + d] + nt6[f[5] * DD + d];
}

// ==================== weight split fp32 -> fp16 hi/lo (both tensors, one launch) ====================
__global__ void wconv_kernel(const float* __restrict__ w1, const float* __restrict__ w2,
                             __half* __restrict__ hi1, __half* __restrict__ lo1,
                             __half* __restrict__ hi2, __half* __restrict__ lo2, int n) {
    int i = blockIdx.x * blockDim.x + threadIdx.x;
    if (i < n) {
        float v = w1[i];
        __half h = __float2half_rn(v);
        hi1[i] = h;
        lo1[i] = __float2half_rn(v - __half2float(h));
    } else if (i < 2 * n) {
        int j = i - n;
        float v = w2[j];
        __half h = __float2half_rn(v);
        hi2[j] = h;
        lo2[j] = __float2half_rn(v - __half2float(h));
    }
}

// ==================== CSR build ====================
__global__ void count_kernel(const int* __restrict__ ei) {
    int e = blockIdx.x * blockDim.x + threadIdx.x;
    if (e >= EE) return;
    atomicAdd(&d_deg[ei[EE + e]], 1);
}

__global__ void scan1_kernel() {
    __shared__ int wsum[32];
    int tid = threadIdx.x;
    int lane = tid & 31, w = tid >> 5;
    int idx = blockIdx.x * 1024 + tid;
    int v = (idx < NN) ? d_deg[idx] : 0;
    int x = v;
#pragma unroll
    for (int o = 1; o < 32; o <<= 1) {
        int y = __shfl_up_sync(0xffffffffu, x, o);
        if (lane >= o) x += y;
    }
    if (lane == 31) wsum[w] = x;
    __syncthreads();
    if (w == 0) {
        int s = wsum[lane];
#pragma unroll
        for (int o = 1; o < 32; o <<= 1) {
            int y = __shfl_up_sync(0xffffffffu, s, o);
            if (lane >= o) s += y;
        }
        wsum[lane] = s;
    }
    __syncthreads();
    int incl = x + ((w > 0) ? wsum[w - 1] : 0);
    if (idx < NN) d_off[idx] = incl - v;
    if (tid == 1023) d_bsum[blockIdx.x] = incl;
}

__global__ void scan2_kernel(int nblk) {
    int lane = threadIdx.x;
    int v = (lane < nblk) ? d_bsum[lane] : 0;
    int x = v;
#pragma unroll
    for (int o = 1; o < 32; o <<= 1) {
        int y = __shfl_up_sync(0xffffffffu, x, o);
        if (lane >= o) x += y;
    }
    if (lane < nblk) d_boff[lane] = x - v;
}

__global__ void scan3_kernel() {
    int idx = blockIdx.x * 1024 + threadIdx.x;
    if (idx < NN) {
        int o = d_off[idx] + d_boff[blockIdx.x];
        d_off[idx] = o;
        d_cur[idx] = o;
    }
    if (idx == 0) d_off[NN] = EE;
}

__global__ void fill_kernel(const int* __restrict__ ei, const int* __restrict__ ea) {
    int e = blockIdx.x * blockDim.x + threadIdx.x;
    if (e >= EE) return;
    int src = ei[e];
    int dst = ei[EE + e];
    int combo = (ea[e * 5 + 0] & 1) | ((ea[e * 5 + 1] & 1) << 1) | ((ea[e * 5 + 2] & 1) << 2)
              | ((ea[e * 5 + 3] & 1) << 3) | ((ea[e * 5 + 4] & 1) << 4);
    int pos = atomicAdd(&d_cur[dst], 1);
    d_csr[pos] = src | (combo << 16);
}

// ==================== ALL layers' combo tables, one launch (+ initial stats zero) ====================
__global__ void ctab_all_kernel(const float* __restrict__ et1, const float* __restrict__ et2,
                                const float* __restrict__ et3, const float* __restrict__ et4,
                                const float* __restrict__ et5) {
    int l = blockIdx.x / 33;
    int c = blockIdx.x % 33;
    int d = threadIdx.x;
    if (blockIdx.x == 0) { d_colsum[d] = 0.0; d_colsq[d] = 0.0; }
    float v;
    if (c == 32) {
        v = et1[(l * 5 + 4) * DD + d] + et2[(l * 4 + 0) * DD + d] + et3[(l * 2 + 0) * DD + d]
          + et4[(l * 2 + 0) * DD + d] + et5[(l * 2 + 0) * DD + d];
    } else {
        v = et1[(l * 5 + (c & 1)) * DD + d] + et2[(l * 4 + ((c >> 1) & 1)) * DD + d]
          + et3[(l * 2 + ((c >> 2) & 1)) * DD + d] + et4[(l * 2 + ((c >> 3) & 1)) * DD + d]
          + et5[(l * 2 + ((c >> 4) & 1)) * DD + d];
    }
    d_ctab[(l * 33 + c) * DD + d] = v;
}

// ==================== SpMM: warp per node, 4-edge unroll, fused BN affine ====================
__device__ __forceinline__ void store_hilo4(__half* hi, __half* lo, float4 v) {
    __half h0 = __float2half_rn(v.x), h1 = __float2half_rn(v.y);
    __half h2 = __float2half_rn(v.z), h3 = __float2half_rn(v.w);
    ((__half2*)hi)[0] = __halves2half2(h0, h1);
    ((__half2*)hi)[1] = __halves2half2(h2, h3);
    __half l0 = __float2half_rn(v.x - __half2float(h0));
    __half l1 = __float2half_rn(v.y - __half2float(h1));
    __half l2 = __float2half_rn(v.z - __half2float(h2));
    __half l3 = __float2half_rn(v.w - __half2float(h3));
    ((__half2*)lo)[0] = __halves2half2(l0, l1);
    ((__half2*)lo)[1] = __halves2half2(l2, l3);
}

// APPLY=0: X already activated (layer 0).  APPLY=1: X raw hh; apply relu(x*sc+sh) on the fly.
template <int APPLY>
__global__ __launch_bounds__(256) void spmm_kernel(const float* __restrict__ X,
                                                   const float* __restrict__ ctab) {
    int node = (blockIdx.x << 3) + (threadIdx.x >> 5);
    int lane = threadIdx.x & 31;
    if (node >= NN) return;
    const float4* __restrict__ x4 = (const float4*)X;
    const float4* __restrict__ ct4 = (const float4*)ctab;
    float4 sc0, sc1, sh0, sh1;
    if (APPLY) {
        sc0 = ((const float4*)d_scale)[lane];
        sc1 = ((const float4*)d_scale)[32 + lane];
        sh0 = ((const float4*)d_shift)[lane];
        sh1 = ((const float4*)d_shift)[32 + lane];
    }
    int i0 = node * 64 + lane;
    float4 a0 = x4[i0];
    float4 a1 = x4[i0 + 32];
    if (APPLY) { a0 = aff4(a0, sc0, sh0); a1 = aff4(a1, sc1, sh1); }
    acc4(a0, ct4[2048 + lane]);
    acc4(a1, ct4[2048 + 32 + lane]);
    int p0 = d_off[node], p1 = d_off[node + 1];
    for (int base = p0; base < p1; base += 32) {
        int cnt = p1 - base;
        if (cnt > 32) cnt = 32;
        int e = (lane < cnt) ? d_csr[base + lane] : 0;
        int j = 0;
        for (; j + 4 <= cnt; j += 4) {
            int e0 = __shfl_sync(0xffffffffu, e, j);
            int e1 = __shfl_sync(0xffffffffu, e, j + 1);
            int e2 = __shfl_sync(0xffffffffu, e, j + 2);
            int e3 = __shfl_sync(0xffffffffu, e, j + 3);
            int sA = (e0 & 0xFFFF) << 6, cA = (e0 >> 16) << 6;
            int sB = (e1 & 0xFFFF) << 6, cB = (e1 >> 16) << 6;
            int sC = (e2 & 0xFFFF) << 6, cC = (e2 >> 16) << 6;
            int sD = (e3 & 0xFFFF) << 6, cD = (e3 >> 16) << 6;
            float4 hA0 = x4[sA + lane], hB0 = x4[sB + lane];
            float4 hC0 = x4[sC + lane], hD0 = x4[sD + lane];
            float4 hA1 = x4[sA + 32 + lane], hB1 = x4[sB + 32 + lane];
            float4 hC1 = x4[sC + 32 + lane], hD1 = x4[sD + 32 + lane];
            if (APPLY) {
                hA0 = aff4(hA0, sc0, sh0); hB0 = aff4(hB0, sc0, sh0);
                hC0 = aff4(hC0, sc0, sh0); hD0 = aff4(hD0, sc0, sh0);
                hA1 = aff4(hA1, sc1, sh1); hB1 = aff4(hB1, sc1, sh1);
                hC1 = aff4(hC1, sc1, sh1); hD1 = aff4(hD1, sc1, sh1);
            }
            acc4(a0, hA0); acc4(a0, hB0); acc4(a0, hC0); acc4(a0, hD0);
            acc4(a1, hA1); acc4(a1, hB1); acc4(a1, hC1); acc4(a1, hD1);
            acc4(a0, ct4[cA + lane]); acc4(a0, ct4[cB + lane]);
            acc4(a0, ct4[cC + lane]); acc4(a0, ct4[cD + lane]);
            acc4(a1, ct4[cA + 32 + lane]); acc4(a1, ct4[cB + 32 + lane]);
            acc4(a1, ct4[cC + 32 + lane]); acc4(a1, ct4[cD + 32 + lane]);
        }
        for (; j < cnt; j++) {
            int e0 = __shfl_sync(0xffffffffu, e, j);
            int sA = (e0 & 0xFFFF) << 6, cA = (e0 >> 16) << 6;
            float4 hA0 = x4[sA + lane], hA1 = x4[sA + 32 + lane];
            if (APPLY) { hA0 = aff4(hA0, sc0, sh0); hA1 = aff4(hA1, sc1, sh1); }
            acc4(a0, hA0); acc4(a0, ct4[cA + lane]);
            acc4(a1, hA1); acc4(a1, ct4[cA + 32 + lane]);
        }
    }
    size_t ob = (size_t)node * 256 + lane * 4;
    store_hilo4(d_aggr_hi + ob, d_aggr_lo + ob, a0);
    store_hilo4(d_aggr_hi + ob + 128, d_aggr_lo + ob + 128, a1);
}

// ==================== HMMA GEMM with cp.async pipeline (128x128, 2 CTA/SM) ====================
#define TILE_B 10240
#define GSMEM (2 * 4 * TILE_B)

template <int OUTF32>
__global__ __launch_bounds__(256, 2) void gemm_hmma(
    float* __restrict__ C, __half* __restrict__ Chi, __half* __restrict__ Clo,
    const __half* __restrict__ Ahi, const __half* __restrict__ Alo,
    const __half* __restrict__ Whi, const __half* __restrict__ Wlo,
    const float* __restrict__ bias, int nrows, int K, int M, int dorelu) {
    extern __shared__ char dynsmem[];
    const uint32_t sbase = smem_u32(dynsmem);

    const int tid = threadIdx.x;
    const int lane = tid & 31;
    const int wid = tid >> 5;
    const int warp_m = wid & 3;
    const int warp_n = wid >> 2;
    const int br = blockIdx.y * 128, bc = blockIdx.x * 128;

    float c[2][8][4];
#pragma unroll
    for (int i = 0; i < 2; i++)
#pragma unroll
        for (int j = 0; j < 8; j++)
#pragma unroll
            for (int k = 0; k < 4; k++) c[i][j][k] = 0.f;

    const int lrow = tid >> 1;
    const int lhalf = (tid & 1) * 16;
    const bool aval = (br + lrow) < nrows;
    const __half* gAh = (aval ? (Ahi + (size_t)(br + lrow) * K) : Ahi) + lhalf;
    const __half* gAl = (aval ? (Alo + (size_t)(br + lrow) * K) : Alo) + lhalf;
    const __half* gWh = Whi + (size_t)(bc + lrow) * K + lhalf;
    const __half* gWl = Wlo + (size_t)(bc + lrow) * K + lhalf;
    const uint32_t dst_off = lrow * 80 + (tid & 1) * 32;
    const int asz = aval ? 16 : 0;

    const int nchunk = K >> 5;

    {
        uint32_t d0 = sbase + dst_off;
        cp16(d0 + 0 * TILE_B, gAh, asz);       cp16(d0 + 0 * TILE_B + 16, gAh + 8, asz);
        cp16(d0 + 1 * TILE_B, gAl, asz);       cp16(d0 + 1 * TILE_B + 16, gAl + 8, asz);
        cp16(d0 + 2 * TILE_B, gWh, 16);        cp16(d0 + 2 * TILE_B + 16, gWh + 8, 16);
        cp16(d0 + 3 * TILE_B, gWl, 16);        cp16(d0 + 3 * TILE_B + 16, gWl + 8, 16);
        cp_commit();
    }

    const int lm_row = lane & 15;
    const int lm_kb = (lane & 16) ? 16 : 0;

    for (int kc = 0; kc < nchunk; kc++) {
        if (kc + 1 < nchunk) {
            uint32_t dn = sbase + ((kc + 1) & 1) * (4 * TILE_B) + dst_off;
            int go = (kc + 1) * 32;
            cp16(dn + 0 * TILE_B, gAh + go, asz); cp16(dn + 0 * TILE_B + 16, gAh + go + 8, asz);
            cp16(dn + 1 * TILE_B, gAl + go, asz); cp16(dn + 1 * TILE_B + 16, gAl + go + 8, asz);
            cp16(dn + 2 * TILE_B, gWh + go, 16);  cp16(dn + 2 * TILE_B + 16, gWh + go + 8, 16);
            cp16(dn + 3 * TILE_B, gWl + go, 16);  cp16(dn + 3 * TILE_B + 16, gWl + go + 8, 16);
            cp_commit();
            cp_wait<1>();
        } else {
            cp_wait<0>();
        }
        __syncthreads();

        const uint32_t bb = sbase + (kc & 1) * (4 * TILE_B);
#pragma unroll
        for (int kk = 0; kk < 2; kk++) {
            const int kbyte = kk * 32 + lm_kb;
            uint32_t ah[2][4], al[2][4];
#pragma unroll
            for (int mf = 0; mf < 2; mf++) {
                int row = warp_m * 32 + mf * 16 + lm_row;
                ldsm_x4(ah[mf], bb + 0 * TILE_B + row * 80 + kbyte);
                ldsm_x4(al[mf], bb + 1 * TILE_B + row * 80 + kbyte);
            }
#pragma unroll
            for (int nf4 = 0; nf4 < 4; nf4++) {
                int row = warp_n * 64 + nf4 * 16 + lm_row;
                uint32_t bh[4], bl[4];
                ldsm_x4(bh, bb + 2 * TILE_B + row * 80 + kbyte);
                ldsm_x4(bl, bb + 3 * TILE_B + row * 80 + kbyte);
                uint32_t bh0[2] = {bh[0], bh[2]}, bh1[2] = {bh[1], bh[3]};
                uint32_t bl0[2] = {bl[0], bl[2]}, bl1[2] = {bl[1], bl[3]};
#pragma unroll
                for (int mf = 0; mf < 2; mf++) {
                    mma_16816(c[mf][nf4 * 2 + 0], ah[mf], bh0);
                    mma_16816(c[mf][nf4 * 2 + 0], ah[mf], bl0);
                    mma_16816(c[mf][nf4 * 2 + 0], al[mf], bh0);
                    mma_16816(c[mf][nf4 * 2 + 1], ah[mf], bh1);
                    mma_16816(c[mf][nf4 * 2 + 1], ah[mf], bl1);
                    mma_16816(c[mf][nf4 * 2 + 1], al[mf], bh1);
                }
            }
        }
        __syncthreads();
    }

    const int erow = lane >> 2;
    const int ecol = (lane & 3) * 2;
#pragma unroll
    for (int mf = 0; mf < 2; mf++) {
#pragma unroll
        for (int half_ = 0; half_ < 2; half_++) {
            int r = br + warp_m * 32 + mf * 16 + erow + half_ * 8;
            bool ok = r < nrows;
            if (!ok) continue;
#pragma unroll
            for (int nf = 0; nf < 8; nf++) {
                int col = bc + warp_n * 64 + nf * 8 + ecol;
                float v0 = c[mf][nf][half_ * 2 + 0] + bias[col];
                float v1 = c[mf][nf][half_ * 2 + 1] + bias[col + 1];
                if (dorelu) { v0 = fmaxf(v0, 0.f); v1 = fmaxf(v1, 0.f); }
                if (OUTF32) {
                    *(float2*)(C + (size_t)r * M + col) = make_float2(v0, v1);
                } else {
                    __half h0 = __float2half_rn(v0);
                    __half h1 = __float2half_rn(v1);
                    __half l0 = __float2half_rn(v0 - __half2float(h0));
                    __half l1 = __float2half_rn(v1 - __half2float(h1));
                    *(__half2*)(Chi + (size_t)r * M + col) = __halves2half2(h0, h1);
                    *(__half2*)(Clo + (size_t)r * M + col) = __halves2half2(l0, l1);
                }
            }
        }
    }
}

// ==================== proj-head GEMM with per-block stats partials ====================
__global__ void gemm64s(float* __restrict__ C, const float* __restrict__ A,
                        const float* __restrict__ W, int nrows, int K, int M) {
    __shared__ float As[64][17];
    __shared__ float Ws[64][17];
    __shared__ float sred[16][68];
    int tid = threadIdx.x;
    int br = blockIdx.y * 64;
    int bc = blockIdx.x * 64;
    int ty = tid / 16, tx = tid % 16;
    int lr = tid / 4;
    int lc = (tid % 4) * 4;
    float acc[4][4];
#pragma unroll
    for (int i = 0; i < 4; i++)
#pragma unroll
        for (int j = 0; j < 4; j++) acc[i][j] = 0.f;
    for (int k0 = 0; k0 < K; k0 += 16) {
        {
            float4 v = *(const float4*)(A + (size_t)(br + lr) * K + k0 + lc);
            As[lr][lc + 0] = v.x; As[lr][lc + 1] = v.y;
            As[lr][lc + 2] = v.z; As[lr][lc + 3] = v.w;
        }
        {
            float4 v = *(const float4*)(W + (size_t)(bc + lr) * K + k0 + lc);
            Ws[lr][lc + 0] = v.x; Ws[lr][lc + 1] = v.y;
            Ws[lr][lc + 2] = v.z; Ws[lr][lc + 3] = v.w;
        }
        __syncthreads();
#pragma unroll
        for (int kk = 0; kk < 16; kk++) {
            float a[4], b[4];
#pragma unroll
            for (int i = 0; i < 4; i++) a[i] = As[ty * 4 + i][kk];
#pragma unroll
            for (int j = 0; j < 4; j++) b[j] = Ws[tx * 4 + j][kk];
#pragma unroll
            for (int i = 0; i < 4; i++)
#pragma unroll
                for (int j = 0; j < 4; j++) acc[i][j] = fmaf(a[i], b[j], acc[i][j]);
        }
        __syncthreads();
    }
#pragma unroll
    for (int i = 0; i < 4; i++) {
        int r = br + ty * 4 + i;
#pragma unroll
        for (int j = 0; j < 4; j++)
            C[(size_t)r * M + bc + tx * 4 + j] = acc[i][j];
    }
#pragma unroll
    for (int j = 0; j < 4; j++)
        sred[ty][tx * 4 + j] = acc[0][j] + acc[1][j] + acc[2][j] + acc[3][j];
    __syncthreads();
    if (tid < 64) {
        float s = 0.f;
#pragma unroll
        for (int y = 0; y < 16; y++) s += sred[y][tid];
        d_pp[blockIdx.y * DD + bc + tid] = s;
    }
    __syncthreads();
#pragma unroll
    for (int j = 0; j < 4; j++)
        sred[ty][tx * 4 + j] = acc[0][j] * acc[0][j] + acc[1][j] * acc[1][j]
                             + acc[2][j] * acc[2][j] + acc[3][j] * acc[3][j];
    __syncthreads();
    if (tid < 64) {
        float q = 0.f;
#pragma unroll
        for (int y = 0; y < 16; y++) q += sred[y][tid];
        d_pq[blockIdx.y * DD + bc + tid] = q;
    }
}

__global__ void bn_affine_proj(float* __restrict__ outp, const float* __restrict__ X,
                               const float* __restrict__ g, const float* __restrict__ b,
                               int dorelu) {
    int i = blockIdx.x, d = threadIdx.x;
    float s = d_pp[d] + d_pp[DD + d] + d_pp[2 * DD + d] + d_pp[3 * DD + d];
    float q = d_pq[d] + d_pq[DD + d] + d_pq[2 * DD + d] + d_pq[3 * DD + d];
    float m = s / (float)GG;
    float var = q / (float)GG - m * m;
    float inv = rsqrtf(var + EPSV);
    float sc = g[d] * inv;
    float sh = b[d] - m * sc;
    float v = fmaf(X[(size_t)i * DD + d], sc, sh);
    if (dorelu) v = fmaxf(v, 0.f);
    outp[(size_t)i * DD + d] = v;
}

// ==================== BN: colstats + fused last-block prepare (+ self-zeroing) ====================
__global__ void colstats_fused(const float* __restrict__ X, int nrows,
                               const float* __restrict__ g, const float* __restrict__ b) {
    int t = threadIdx.x;
    int r0 = blockIdx.x * 64;
    int rend = min(r0 + 64, nrows);
    float s = 0.f, ss = 0.f;
    for (int r = r0; r < rend; r++) {
        float v = X[(size_t)r * DD + t];
        s += v;
        ss += v * v;
    }
    atomicAdd(&d_colsum[t], (double)s);
    atomicAdd(&d_colsq[t], (double)ss);
    __threadfence();
    __shared__ int isLast;
    if (t == 0) isLast = (atomicAdd(&d_lastblk, 1) == (int)gridDim.x - 1);
    __syncthreads();
    if (isLast) {
        if (t == 0) d_lastblk = 0;  // self-reset for next launch/replay
        double m = d_colsum[t] / (double)nrows;
        double var = d_colsq[t] / (double)nrows - m * m;
        // reset accumulators for the next layer (read complete above)
        d_colsum[t] = 0.0;
        d_colsq[t] = 0.0;
        float inv = rsqrtf((float)var + EPSV);
        float sc = g[t] * inv;
        d_scale[t] = sc;
        d_shift[t] = b[t] - (float)m * sc;
    }
}

// ==================== pooling (binary-search boundaries + fused BN affine/relu) ====================
__global__ void pool_kernel(const int* __restrict__ batch) {
    int g = blockIdx.x, d = threadIdx.x;
    __shared__ int sb[2];
    if (d < 2) {
        int target = g + d;
        int lo = 0, hi = NN;
        while (lo < hi) {
            int mid = (lo + hi) >> 1;
            if (batch[mid] < target) lo = mid + 1; else hi = mid;
        }
        sb[d] = lo;
    }
    __syncthreads();
    int s0 = sb[0], s1 = sb[1];
    float sc = d_scale[d], sh = d_shift[d];
    float acc = 0.f;
    for (int i = s0; i < s1; i++)
        acc += fmaxf(fmaf(d_hh[(size_t)i * DD + d], sc, sh), 0.f);
    int c = s1 - s0;
    if (c < 1) c = 1;
    d_hg[(size_t)g * DD + d] = acc / (float)c;
}

// ==================== output MLP ====================
__global__ void out_kernel(float* __restrict__ outp,
                           const float* __restrict__ ow1, const float* __restrict__ ob1,
                           const float* __restrict__ ow2, const float* __restrict__ ob2) {
    int g = blockIdx.x;
    int t = threadIdx.x;
    __shared__ float sp[128];
    const float* row = d_hg + (size_t)g * DD;
    float acc = ob1[t];
    for (int k = 0; k < DD; k++) acc = fmaf(row[k], ow1[t * DD + k], acc);
    float v = (acc > 20.f) ? acc : log1pf(expf(acc));
    sp[t] = v;
    __syncthreads();
    if (t < 2) {
        float o = ob2[t];
        for (int k = 0; k < 128; k++) o = fmaf(sp[k], ow2[t * 128 + k], o);
        outp[g * 2 + t] = o;
    }
}

// ==================== launch ====================
extern "C" void kernel_launch(void* const* d_in, const int* in_sizes, int n_in,
                              void* d_out, int out_size) {
    const int* xf = (const int*)d_in[0];
    const int* ei = (const int*)d_in[1];
    const int* ea = (const int*)d_in[2];
    const int* batch = (const int*)d_in[3];
    const float* nt1 = (const float*)d_in[4];
    const float* nt2 = (const float*)d_in[5];
    const float* nt3 = (const float*)d_in[6];
    const float* nt4 = (const float*)d_in[7];
    const float* nt5 = (const float*)d_in[8];
    const float* nt6 = (const float*)d_in[9];
    const float* et1 = (const float*)d_in[10];
    const float* et2 = (const float*)d_in[11];
    const float* et3 = (const float*)d_in[12];
    const float* et4 = (const float*)d_in[13];
    const float* et5 = (const float*)d_in[14];
    const float* w1 = (const float*)d_in[15];
    const float* b1 = (const float*)d_in[16];
    const float* w2 = (const float*)d_in[17];
    const float* b2 = (const float*)d_in[18];
    const float* bng = (const float*)d_in[19];
    const float* bnb = (const float*)d_in[20];
    const float* pw = (const float*)d_in[21];
    const float* pg = (const float*)d_in[22];
    const float* pb = (const float*)d_in[23];
    const float* ow1 = (const float*)d_in[24];
    const float* ob1 = (const float*)d_in[25];
    const float* ow2 = (const float*)d_in[26];
    const float* ob2 = (const float*)d_in[27];
    float* outp = (float*)d_out;

    float *p_h, *p_hh, *p_hg, *p_hg2, *p_ctab;
    __half *p_ahi, *p_alo, *p_hhi, *p_hlo, *p_w1hi, *p_w1lo, *p_w2hi, *p_w2lo;
    cudaGetSymbolAddress((void**)&p_h, d_h);
    cudaGetSymbolAddress((void**)&p_hh, d_hh);
    cudaGetSymbolAddress((void**)&p_hg, d_hg);
    cudaGetSymbolAddress((void**)&p_hg2, d_hg2);
    cudaGetSymbolAddress((void**)&p_ctab, d_ctab);
    cudaGetSymbolAddress((void**)&p_ahi, d_aggr_hi);
    cudaGetSymbolAddress((void**)&p_alo, d_aggr_lo);
    cudaGetSymbolAddress((void**)&p_hhi, d_hid_hi);
    cudaGetSymbolAddress((void**)&p_hlo, d_hid_lo);
    cudaGetSymbolAddress((void**)&p_w1hi, d_w1hi);
    cudaGetSymbolAddress((void**)&p_w1lo, d_w1lo);
    cudaGetSymbolAddress((void**)&p_w2hi, d_w2hi);
    cudaGetSymbolAddress((void**)&p_w2lo, d_w2lo);

    cudaFuncSetAttribute(gemm_hmma<0>, cudaFuncAttributeMaxDynamicSharedMemorySize, GSMEM);
    cudaFuncSetAttribute(gemm_hmma<1>, cudaFuncAttributeMaxDynamicSharedMemorySize, GSMEM);

    embed_kernel<<<NN, DD>>>(xf, nt1, nt2, nt3, nt4, nt5, nt6);

    const int WN = LL * 2 * DD * DD;
    wconv_kernel<<<(2 * WN + 255) / 256, 256>>>(w1, w2, p_w1hi, p_w1lo, p_w2hi, p_w2lo, WN);

    // all 5 layers' combo tables + initial stats zero, one launch
    ctab_all_kernel<<<LL * 33, DD>>>(et1, et2, et3, et4, et5);

    const int SBLK = (NN + 1023) / 1024;  // 20
    count_kernel<<<(EE + 255) / 256, 256>>>(ei);
    scan1_kernel<<<SBLK, 1024>>>();
    scan2_kernel<<<1, 32>>>(SBLK);
    scan3_kernel<<<SBLK, 1024>>>();
    fill_kernel<<<(EE + 255) / 256, 256>>>(ei, ea);

    const int GY = (NN + 127) / 128;  // 157
    for (int l = 0; l < LL; l++) {
        const float* ctab_l = p_ctab + (size_t)l * 33 * DD;
        if (l == 0)
            spmm_kernel<0><<<NN / 8, 256>>>(p_h, ctab_l);
        else
            spmm_kernel<1><<<NN / 8, 256>>>(p_hh, ctab_l);
        gemm_hmma<0><<<dim3(4, GY), 256, GSMEM>>>(
            nullptr, p_hhi, p_hlo, p_ahi, p_alo,
            p_w1hi + (size_t)l * 2 * DD * DD, p_w1lo + (size_t)l * 2 * DD * DD,
            b1 + (size_t)l * 2 * DD, NN, DD, 2 * DD, 1);
        gemm_hmma<1><<<dim3(2, GY), 256, GSMEM>>>(
            p_hh, nullptr, nullptr, p_hhi, p_hlo,
            p_w2hi + (size_t)l * 2 * DD * DD, p_w2lo + (size_t)l * 2 * DD * DD,
            b2 + (size_t)l * DD, NN, 2 * DD, DD, 0);
        colstats_fused<<<(NN + 63) / 64, DD>>>(p_hh, NN,
                                               bng + (size_t)l * DD, bnb + (size_t)l * DD);
    }

    // pooling (applies layer-5 BN affine + relu inline; boundaries via binary search)
    pool_kernel<<<GG, DD>>>(batch);

    for (int i = 0; i < 3; i++) {
        gemm64s<<<dim3(4, 4), 256>>>(p_hg2, p_hg, pw + (size_t)i * DD * DD, GG, DD, DD);
        bn_affine_proj<<<GG, DD>>>(p_hg, p_hg2, pg + (size_t)i * DD, pb + (size_t)i * DD,
                                   (i < 2) ? 1 : 0);
    }

    out_kernel<<<GG, 128>>>(outp, ow1, ob1, ow2, ob2);
}

// round 16
// speedup vs baseline: 1.1867x; 1.0038x over previous
#include <cuda_runtime.h>
#include <cuda_fp16.h>
#include <math.h>
#include <stdint.h>

#define NN 20000
#define EE 320000
#define GG 256
#define DD 256
#define LL 5
#define EPSV 1e-5f

// ==================== device scratch ====================
__device__ float d_h[NN * DD];
__device__ float d_hh[NN * DD];
__device__ __half d_aggr_hi[NN * DD];
__device__ __half d_aggr_lo[NN * DD];
__device__ __half d_hid_hi[NN * 2 * DD];
__device__ __half d_hid_lo[NN * 2 * DD];
__device__ __half d_w1hi[LL * 2 * DD * DD];
__device__ __half d_w1lo[LL * 2 * DD * DD];
__device__ __half d_w2hi[LL * 2 * DD * DD];
__device__ __half d_w2lo[LL * 2 * DD * DD];
__device__ double d_colsum[DD];
__device__ double d_colsq[DD];
__device__ float d_scale[DD];
__device__ float d_shift[DD];
__device__ float d_hg[GG * DD];
__device__ float d_hg2[GG * DD];
__device__ float d_pp[4 * DD];
__device__ float d_pq[4 * DD];
__device__ float d_ctab[LL * 33 * DD];
__device__ int d_deg[NN];
__device__ int d_off[NN + 1];
__device__ int d_cur[NN];
__device__ int d_csr[EE];
__device__ int d_bsum[32];
__device__ int d_boff[32];
__device__ int d_lastblk;

// ==================== PTX helpers ====================
__device__ __forceinline__ uint32_t smem_u32(const void* p) {
    uint32_t a;
    asm("{ .reg .u64 t; cvta.to.shared.u64 t, %1; cvt.u32.u64 %0, t; }" : "=r"(a) : "l"(p));
    return a;
}

__device__ __forceinline__ void ldsm_x4(uint32_t* r, uint32_t addr) {
    asm volatile("ldmatrix.sync.aligned.m8n8.x4.shared.b16 {%0,%1,%2,%3}, [%4];"
                 : "=r"(r[0]), "=r"(r[1]), "=r"(r[2]), "=r"(r[3]) : "r"(addr));
}

__device__ __forceinline__ void mma_16816(float* d, const uint32_t* a, const uint32_t* b) {
    asm volatile(
        "mma.sync.aligned.m16n8k16.row.col.f32.f16.f16.f32 "
        "{%0,%1,%2,%3}, {%4,%5,%6,%7}, {%8,%9}, {%0,%1,%2,%3};"
        : "+f"(d[0]), "+f"(d[1]), "+f"(d[2]), "+f"(d[3])
        : "r"(a[0]), "r"(a[1]), "r"(a[2]), "r"(a[3]), "r"(b[0]), "r"(b[1]));
}

__device__ __forceinline__ void cp16(uint32_t dst, const void* src, int srcsz) {
    asm volatile("cp.async.cg.shared.global [%0], [%1], 16, %2;"
                 :: "r"(dst), "l"(src), "r"(srcsz) : "memory");
}
__device__ __forceinline__ void cp_commit() {
    asm volatile("cp.async.commit_group;" ::: "memory");
}
template <int N>
__device__ __forceinline__ void cp_wait() {
    asm volatile("cp.async.wait_group %0;" :: "n"(N) : "memory");
}

__device__ __forceinline__ void acc4(float4& a, const float4 b) {
    a.x += b.x; a.y += b.y; a.z += b.z; a.w += b.w;
}
__device__ __forceinline__ float4 aff4(float4 x, const float4 sc, const float4 sh) {
    float4 r;
    r.x = fmaxf(fmaf(x.x, sc.x, sh.x), 0.f);
    r.y = fmaxf(fmaf(x.y, sc.y, sh.y), 0.f);
    r.z = fmaxf(fmaf(x.z, sc.z, sh.z), 0.f);
    r.w = fmaxf(fmaf(x.w, sc.w, sh.w), 0.f);
    return r;
}

// ==================== embeddings (+ deg zero fused) ====================
__global__ void embed_kernel(const int* __restrict__ xf,
                             const float* __restrict__ nt1, const float* __restrict__ nt2,
                             const float* __restrict__ nt3, const float* __restrict__ nt4,
                             const float* __restrict__ nt5, const float* __restrict__ nt6) {
    int i = blockIdx.x;
    int d = threadIdx.x;
    __shared__ int f[6];
    if (d < 6) f[d] = xf[i * 6 + d];
    if (d == 6) d_deg[i] = 0;
    __syncthreads();
    d_h[i * DD + d] = nt1[f[0] * DD + d] + nt2[f[1] * DD + d] + nt3[f[2] * DD + d]
                    + nt4[f[3] * DD + d] + nt5[f[4] * DD + d] + nt6[f[5] * DD + d];
}

// ==================== weight split fp32 -> fp16 hi/lo ====================
__global__ void wconv_kernel(const float* __restrict__ w1, const float* __restrict__ w2,
                             __half* __restrict__ hi1, __half* __restrict__ lo1,
                             __half* __restrict__ hi2, __half* __restrict__ lo2, int n) {
    int i = blockIdx.x * blockDim.x + threadIdx.x;
    if (i < n) {
        float v = w1[i];
        __half h = __float2half_rn(v);
        hi1[i] = h;
        lo1[i] = __float2half_rn(v - __half2float(h));
    } else if (i < 2 * n) {
        int j = i - n;
        float v = w2[j];
        __half h = __float2half_rn(v);
        hi2[j] = h;
        lo2[j] = __float2half_rn(v - __half2float(h));
    }
}

// ==================== CSR build ====================
__global__ void count_kernel(const int* __restrict__ ei) {
    int e = blockIdx.x * blockDim.x + threadIdx.x;
    if (e >= EE) return;
    atomicAdd(&d_deg[ei[EE + e]], 1);
}

__global__ void scan1_kernel() {
    __shared__ int wsum[32];
    int tid = threadIdx.x;
    int lane = tid & 31, w = tid >> 5;
    int idx = blockIdx.x * 1024 + tid;
    int v = (idx < NN) ? d_deg[idx] : 0;
    int x = v;
#pragma unroll
    for (int o = 1; o < 32; o <<= 1) {
        int y = __shfl_up_sync(0xffffffffu, x, o);
        if (lane >= o) x += y;
    }
    if (lane == 31) wsum[w] = x;
    __syncthreads();
    if (w == 0) {
        int s = wsum[lane];
#pragma unroll
        for (int o = 1; o < 32; o <<= 1) {
            int y = __shfl_up_sync(0xffffffffu, s, o);
            if (lane >= o) s += y;
        }
        wsum[lane] = s;
    }
    __syncthreads();
    int incl = x + ((w > 0) ? wsum[w - 1] : 0);
    if (idx < NN) d_off[idx] = incl - v;
    if (tid == 1023) d_bsum[blockIdx.x] = incl;
}

__global__ void scan2_kernel(int nblk) {
    int lane = threadIdx.x;
    int v = (lane < nblk) ? d_bsum[lane] : 0;
    int x = v;
#pragma unroll
    for (int o = 1; o < 32; o <<= 1) {
        int y = __shfl_up_sync(0xffffffffu, x, o);
        if (lane >= o) x += y;
    }
    if (lane < nblk) d_boff[lane] = x - v;
}

__global__ void scan3_kernel() {
    int idx = blockIdx.x * 1024 + threadIdx.x;
    if (idx < NN) {
        int o = d_off[idx] + d_boff[blockIdx.x];
        d_off[idx] = o;
        d_cur[idx] = o;
    }
    if (idx == 0) d_off[NN] = EE;
}

__global__ void fill_kernel(const int* __restrict__ ei, const int* __restrict__ ea) {
    int e = blockIdx.x * blockDim.x + threadIdx.x;
    if (e >= EE) return;
    int src = ei[e];
    int dst = ei[EE + e];
    int combo = (ea[e * 5 + 0] & 1) | ((ea[e * 5 + 1] & 1) << 1) | ((ea[e * 5 + 2] & 1) << 2)
              | ((ea[e * 5 + 3] & 1) << 3) | ((ea[e * 5 + 4] & 1) << 4);
    int pos = atomicAdd(&d_cur[dst], 1);
    d_csr[pos] = src | (combo << 16);
}

// ==================== all layers' combo tables (+ initial stats zero) ====================
__global__ void ctab_all_kernel(const float* __restrict__ et1, const float* __restrict__ et2,
                                const float* __restrict__ et3, const float* __restrict__ et4,
                                const float* __restrict__ et5) {
    int l = blockIdx.x / 33;
    int c = blockIdx.x % 33;
    int d = threadIdx.x;
    if (blockIdx.x == 0) { d_colsum[d] = 0.0; d_colsq[d] = 0.0; }
    float v;
    if (c == 32) {
        v = et1[(l * 5 + 4) * DD + d] + et2[(l * 4 + 0) * DD + d] + et3[(l * 2 + 0) * DD + d]
          + et4[(l * 2 + 0) * DD + d] + et5[(l * 2 + 0) * DD + d];
    } else {
        v = et1[(l * 5 + (c & 1)) * DD + d] + et2[(l * 4 + ((c >> 1) & 1)) * DD + d]
          + et3[(l * 2 + ((c >> 2) & 1)) * DD + d] + et4[(l * 2 + ((c >> 3) & 1)) * DD + d]
          + et5[(l * 2 + ((c >> 4) & 1)) * DD + d];
    }
    d_ctab[(l * 33 + c) * DD + d] = v;
}

// ==================== SpMM ====================
__device__ __forceinline__ void store_hilo4(__half* hi, __half* lo, float4 v) {
    __half h0 = __float2half_rn(v.x), h1 = __float2half_rn(v.y);
    __half h2 = __float2half_rn(v.z), h3 = __float2half_rn(v.w);
    ((__half2*)hi)[0] = __halves2half2(h0, h1);
    ((__half2*)hi)[1] = __halves2half2(h2, h3);
    __half l0 = __float2half_rn(v.x - __half2float(h0));
    __half l1 = __float2half_rn(v.y - __half2float(h1));
    __half l2 = __float2half_rn(v.z - __half2float(h2));
    __half l3 = __float2half_rn(v.w - __half2float(h3));
    ((__half2*)lo)[0] = __halves2half2(l0, l1);
    ((__half2*)lo)[1] = __halves2half2(l2, l3);
}

template <int APPLY>
__global__ __launch_bounds__(256) void spmm_kernel(const float* __restrict__ X,
                                                   const float* __restrict__ ctab) {
    int node = (blockIdx.x << 3) + (threadIdx.x >> 5);
    int lane = threadIdx.x & 31;
    if (node >= NN) return;
    const float4* __restrict__ x4 = (const float4*)X;
    const float4* __restrict__ ct4 = (const float4*)ctab;
    float4 sc0, sc1, sh0, sh1;
    if (APPLY) {
        sc0 = ((const float4*)d_scale)[lane];
        sc1 = ((const float4*)d_scale)[32 + lane];
        sh0 = ((const float4*)d_shift)[lane];
        sh1 = ((const float4*)d_shift)[32 + lane];
    }
    int i0 = node * 64 + lane;
    float4 a0 = x4[i0];
    float4 a1 = x4[i0 + 32];
    if (APPLY) { a0 = aff4(a0, sc0, sh0); a1 = aff4(a1, sc1, sh1); }
    acc4(a0, ct4[2048 + lane]);
    acc4(a1, ct4[2048 + 32 + lane]);
    int p0 = d_off[node], p1 = d_off[node + 1];
    for (int base = p0; base < p1; base += 32) {
        int cnt = p1 - base;
        if (cnt > 32) cnt = 32;
        int e = (lane < cnt) ? d_csr[base + lane] : 0;
        int j = 0;
        for (; j + 4 <= cnt; j += 4) {
            int e0 = __shfl_sync(0xffffffffu, e, j);
            int e1 = __shfl_sync(0xffffffffu, e, j + 1);
            int e2 = __shfl_sync(0xffffffffu, e, j + 2);
            int e3 = __shfl_sync(0xffffffffu, e, j + 3);
            int sA = (e0 & 0xFFFF) << 6, cA = (e0 >> 16) << 6;
            int sB = (e1 & 0xFFFF) << 6, cB = (e1 >> 16) << 6;
            int sC = (e2 & 0xFFFF) << 6, cC = (e2 >> 16) << 6;
            int sD = (e3 & 0xFFFF) << 6, cD = (e3 >> 16) << 6;
            float4 hA0 = x4[sA + lane], hB0 = x4[sB + lane];
            float4 hC0 = x4[sC + lane], hD0 = x4[sD + lane];
            float4 hA1 = x4[sA + 32 + lane], hB1 = x4[sB + 32 + lane];
            float4 hC1 = x4[sC + 32 + lane], hD1 = x4[sD + 32 + lane];
            if (APPLY) {
                hA0 = aff4(hA0, sc0, sh0); hB0 = aff4(hB0, sc0, sh0);
                hC0 = aff4(hC0, sc0, sh0); hD0 = aff4(hD0, sc0, sh0);
                hA1 = aff4(hA1, sc1, sh1); hB1 = aff4(hB1, sc1, sh1);
                hC1 = aff4(hC1, sc1, sh1); hD1 = aff4(hD1, sc1, sh1);
            }
            acc4(a0, hA0); acc4(a0, hB0); acc4(a0, hC0); acc4(a0, hD0);
            acc4(a1, hA1); acc4(a1, hB1); acc4(a1, hC1); acc4(a1, hD1);
            acc4(a0, ct4[cA + lane]); acc4(a0, ct4[cB + lane]);
            acc4(a0, ct4[cC + lane]); acc4(a0, ct4[cD + lane]);
            acc4(a1, ct4[cA + 32 + lane]); acc4(a1, ct4[cB + 32 + lane]);
            acc4(a1, ct4[cC + 32 + lane]); acc4(a1, ct4[cD + 32 + lane]);
        }
        for (; j < cnt; j++) {
            int e0 = __shfl_sync(0xffffffffu, e, j);
            int sA = (e0 & 0xFFFF) << 6, cA = (e0 >> 16) << 6;
            float4 hA0 = x4[sA + lane], hA1 = x4[sA + 32 + lane];
            if (APPLY) { hA0 = aff4(hA0, sc0, sh0); hA1 = aff4(hA1, sc1, sh1); }
            acc4(a0, hA0); acc4(a0, ct4[cA + lane]);
            acc4(a1, hA1); acc4(a1, ct4[cA + 32 + lane]);
        }
    }
    size_t ob = (size_t)node * 256 + lane * 4;
    store_hilo4(d_aggr_hi + ob, d_aggr_lo + ob, a0);
    store_hilo4(d_aggr_hi + ob + 128, d_aggr_lo + ob + 128, a1);
}

// ==================== HMMA GEMM (128x128, 2 CTA/SM, cp.async, full 3-term) ====================
#define TILE_B 10240
#define GSMEM (2 * 4 * TILE_B)

template <int OUTF32>
__global__ __launch_bounds__(256, 2) void gemm_hmma(
    float* __restrict__ C, __half* __restrict__ Chi, __half* __restrict__ Clo,
    const __half* __restrict__ Ahi, const __half* __restrict__ Alo,
    const __half* __restrict__ Whi, const __half* __restrict__ Wlo,
    const float* __restrict__ bias, int nrows, int K, int M, int dorelu) {
    extern __shared__ char dynsmem[];
    const uint32_t sbase = smem_u32(dynsmem);

    const int tid = threadIdx.x;
    const int lane = tid & 31;
    const int wid = tid >> 5;
    const int warp_m = wid & 3;
    const int warp_n = wid >> 2;
    const int br = blockIdx.y * 128, bc = blockIdx.x * 128;

    float c[2][8][4];
#pragma unroll
    for (int i = 0; i < 2; i++)
#pragma unroll
        for (int j = 0; j < 8; j++)
#pragma unroll
            for (int k = 0; k < 4; k++) c[i][j][k] = 0.f;

    const int lrow = tid >> 1;
    const int lhalf = (tid & 1) * 16;
    const bool aval = (br + lrow) < nrows;
    const __half* gAh = (aval ? (Ahi + (size_t)(br + lrow) * K) : Ahi) + lhalf;
    const __half* gAl = (aval ? (Alo + (size_t)(br + lrow) * K) : Alo) + lhalf;
    const __half* gWh = Whi + (size_t)(bc + lrow) * K + lhalf;
    const __half* gWl = Wlo + (size_t)(bc + lrow) * K + lhalf;
    const uint32_t dst_off = lrow * 80 + (tid & 1) * 32;
    const int asz = aval ? 16 : 0;

    const int nchunk = K >> 5;

    {
        uint32_t d0 = sbase + dst_off;
        cp16(d0 + 0 * TILE_B, gAh, asz);       cp16(d0 + 0 * TILE_B + 16, gAh + 8, asz);
        cp16(d0 + 1 * TILE_B, gAl, asz);       cp16(d0 + 1 * TILE_B + 16, gAl + 8, asz);
        cp16(d0 + 2 * TILE_B, gWh, 16);        cp16(d0 + 2 * TILE_B + 16, gWh + 8, 16);
        cp16(d0 + 3 * TILE_B, gWl, 16);        cp16(d0 + 3 * TILE_B + 16, gWl + 8, 16);
        cp_commit();
    }

    const int lm_row = lane & 15;
    const int lm_kb = (lane & 16) ? 16 : 0;

    for (int kc = 0; kc < nchunk; kc++) {
        if (kc + 1 < nchunk) {
            uint32_t dn = sbase + ((kc + 1) & 1) * (4 * TILE_B) + dst_off;
            int go = (kc + 1) * 32;
            cp16(dn + 0 * TILE_B, gAh + go, asz); cp16(dn + 0 * TILE_B + 16, gAh + go + 8, asz);
            cp16(dn + 1 * TILE_B, gAl + go, asz); cp16(dn + 1 * TILE_B + 16, gAl + go + 8, asz);
            cp16(dn + 2 * TILE_B, gWh + go, 16);  cp16(dn + 2 * TILE_B + 16, gWh + go + 8, 16);
            cp16(dn + 3 * TILE_B, gWl + go, 16);  cp16(dn + 3 * TILE_B + 16, gWl + go + 8, 16);
            cp_commit();
            cp_wait<1>();
        } else {
            cp_wait<0>();
        }
        __syncthreads();

        const uint32_t bb = sbase + (kc & 1) * (4 * TILE_B);
#pragma unroll
        for (int kk = 0; kk < 2; kk++) {
            const int kbyte = kk * 32 + lm_kb;
            uint32_t ah[2][4], al[2][4];
#pragma unroll
            for (int mf = 0; mf < 2; mf++) {
                int row = warp_m * 32 + mf * 16 + lm_row;
                ldsm_x4(ah[mf], bb + 0 * TILE_B + row * 80 + kbyte);
                ldsm_x4(al[mf], bb + 1 * TILE_B + row * 80 + kbyte);
            }
#pragma unroll
            for (int nf4 = 0; nf4 < 4; nf4++) {
                int row = warp_n * 64 + nf4 * 16 + lm_row;
                uint32_t bh[4], bl[4];
                ldsm_x4(bh, bb + 2 * TILE_B + row * 80 + kbyte);
                ldsm_x4(bl, bb + 3 * TILE_B + row * 80 + kbyte);
                uint32_t bh0[2] = {bh[0], bh[2]}, bh1[2] = {bh[1], bh[3]};
                uint32_t bl0[2] = {bl[0], bl[2]}, bl1[2] = {bl[1], bl[3]};
#pragma unroll
                for (int mf = 0; mf < 2; mf++) {
                    mma_16816(c[mf][nf4 * 2 + 0], ah[mf], bh0);
                    mma_16816(c[mf][nf4 * 2 + 0], ah[mf], bl0);
                    mma_16816(c[mf][nf4 * 2 + 0], al[mf], bh0);
                    mma_16816(c[mf][nf4 * 2 + 1], ah[mf], bh1);
                    mma_16816(c[mf][nf4 * 2 + 1], ah[mf], bl1);
                    mma_16816(c[mf][nf4 * 2 + 1], al[mf], bh1);
                }
            }
        }
        __syncthreads();
    }

    const int erow = lane >> 2;
    const int ecol = (lane & 3) * 2;
#pragma unroll
    for (int mf = 0; mf < 2; mf++) {
#pragma unroll
        for (int half_ = 0; half_ < 2; half_++) {
            int r = br + warp_m * 32 + mf * 16 + erow + half_ * 8;
            bool ok = r < nrows;
            if (!ok) continue;
#pragma unroll
            for (int nf = 0; nf < 8; nf++) {
                int col = bc + warp_n * 64 + nf * 8 + ecol;
                float v0 = c[mf][nf][half_ * 2 + 0] + bias[col];
                float v1 = c[mf][nf][half_ * 2 + 1] + bias[col + 1];
                if (dorelu) { v0 = fmaxf(v0, 0.f); v1 = fmaxf(v1, 0.f); }
                if (OUTF32) {
                    *(float2*)(C + (size_t)r * M + col) = make_float2(v0, v1);
                } else {
                    __half h0 = __float2half_rn(v0);
                    __half h1 = __float2half_rn(v1);
                    __half l0 = __float2half_rn(v0 - __half2float(h0));
                    __half l1 = __float2half_rn(v1 - __half2float(h1));
                    *(__half2*)(Chi + (size_t)r * M + col) = __halves2half2(h0, h1);
                    *(__half2*)(Clo + (size_t)r * M + col) = __halves2half2(l0, l1);
                }
            }
        }
    }
}

// ==================== proj-head GEMM with per-block stats partials ====================
__global__ void gemm64s(float* __restrict__ C, const float* __restrict__ A,
                        const float* __restrict__ W, int nrows, int K, int M) {
    __shared__ float As[64][17];
    __shared__ float Ws[64][17];
    __shared__ float sred[16][68];
    int tid = threadIdx.x;
    int br = blockIdx.y * 64;
    int bc = blockIdx.x * 64;
    int ty = tid / 16, tx = tid % 16;
    int lr = tid / 4;
    int lc = (tid % 4) * 4;
    float acc[4][4];
#pragma unroll
    for (int i = 0; i < 4; i++)
#pragma unroll
        for (int j = 0; j < 4; j++) acc[i][j] = 0.f;
    for (int k0 = 0; k0 < K; k0 += 16) {
        {
            float4 v = *(const float4*)(A + (size_t)(br + lr) * K + k0 + lc);
            As[lr][lc + 0] = v.x; As[lr][lc + 1] = v.y;
            As[lr][lc + 2] = v.z; As[lr][lc + 3] = v.w;
        }
        {
            float4 v = *(const float4*)(W + (size_t)(bc + lr) * K + k0 + lc);
            Ws[lr][lc + 0] = v.x; Ws[lr][lc + 1] = v.y;
            Ws[lr][lc + 2] = v.z; Ws[lr][lc + 3] = v.w;
        }
        __syncthreads();
#pragma unroll
        for (int kk = 0; kk < 16; kk++) {
            float a[4], b[4];
#pragma unroll
            for (int i = 0; i < 4; i++) a[i] = As[ty * 4 + i][kk];
#pragma unroll
            for (int j = 0; j < 4; j++) b[j] = Ws[tx * 4 + j][kk];
#pragma unroll
            for (int i = 0; i < 4; i++)
#pragma unroll
                for (int j = 0; j < 4; j++) acc[i][j] = fmaf(a[i], b[j], acc[i][j]);
        }
        __syncthreads();
    }
#pragma unroll
    for (int i = 0; i < 4; i++) {
        int r = br + ty * 4 + i;
#pragma unroll
        for (int j = 0; j < 4; j++)
            C[(size_t)r * M + bc + tx * 4 + j] = acc[i][j];
    }
#pragma unroll
    for (int j = 0; j < 4; j++)
        sred[ty][tx * 4 + j] = acc[0][j] + acc[1][j] + acc[2][j] + acc[3][j];
    __syncthreads();
    if (tid < 64) {
        float s = 0.f;
#pragma unroll
        for (int y = 0; y < 16; y++) s += sred[y][tid];
        d_pp[blockIdx.y * DD + bc + tid] = s;
    }
    __syncthreads();
#pragma unroll
    for (int j = 0; j < 4; j++)
        sred[ty][tx * 4 + j] = acc[0][j] * acc[0][j] + acc[1][j] * acc[1][j]
                             + acc[2][j] * acc[2][j] + acc[3][j] * acc[3][j];
    __syncthreads();
    if (tid < 64) {
        float q = 0.f;
#pragma unroll
        for (int y = 0; y < 16; y++) q += sred[y][tid];
        d_pq[blockIdx.y * DD + bc + tid] = q;
    }
}

__global__ void bn_affine_proj(float* __restrict__ outp, const float* __restrict__ X,
                               const float* __restrict__ g, const float* __restrict__ b,
                               int dorelu) {
    int i = blockIdx.x, d = threadIdx.x;
    float s = d_pp[d] + d_pp[DD + d] + d_pp[2 * DD + d] + d_pp[3 * DD + d];
    float q = d_pq[d] + d_pq[DD + d] + d_pq[2 * DD + d] + d_pq[3 * DD + d];
    float m = s / (float)GG;
    float var = q / (float)GG - m * m;
    float inv = rsqrtf(var + EPSV);
    float sc = g[d] * inv;
    float sh = b[d] - m * sc;
    float v = fmaf(X[(size_t)i * DD + d], sc, sh);
    if (dorelu) v = fmaxf(v, 0.f);
    outp[(size_t)i * DD + d] = v;
}

// ==================== BN: colstats (128 rows/block) + fused last-block prepare ====================
__global__ void colstats_fused(const float* __restrict__ X, int nrows,
                               const float* __restrict__ g, const float* __restrict__ b) {
    int t = threadIdx.x;
    int r0 = blockIdx.x * 128;
    int rend = min(r0 + 128, nrows);
    float s = 0.f, ss = 0.f;
    for (int r = r0; r < rend; r++) {
        float v = X[(size_t)r * DD + t];
        s += v;
        ss += v * v;
    }
    atomicAdd(&d_colsum[t], (double)s);
    atomicAdd(&d_colsq[t], (double)ss);
    __threadfence();
    __shared__ int isLast;
    if (t == 0) isLast = (atomicAdd(&d_lastblk, 1) == (int)gridDim.x - 1);
    __syncthreads();
    if (isLast) {
        if (t == 0) d_lastblk = 0;
        double m = d_colsum[t] / (double)nrows;
        double var = d_colsq[t] / (double)nrows - m * m;
        d_colsum[t] = 0.0;
        d_colsq[t] = 0.0;
        float inv = rsqrtf((float)var + EPSV);
        float sc = g[t] * inv;
        d_scale[t] = sc;
        d_shift[t] = b[t] - (float)m * sc;
    }
}

// ==================== pooling ====================
__global__ void pool_kernel(const int* __restrict__ batch) {
    int g = blockIdx.x, d = threadIdx.x;
    __shared__ int sb[2];
    if (d < 2) {
        int target = g + d;
        int lo = 0, hi = NN;
        while (lo < hi) {
            int mid = (lo + hi) >> 1;
            if (batch[mid] < target) lo = mid + 1; else hi = mid;
        }
        sb[d] = lo;
    }
    __syncthreads();
    int s0 = sb[0], s1 = sb[1];
    float sc = d_scale[d], sh = d_shift[d];
    float acc = 0.f;
    for (int i = s0; i < s1; i++)
        acc += fmaxf(fmaf(d_hh[(size_t)i * DD + d], sc, sh), 0.f);
    int c = s1 - s0;
    if (c < 1) c = 1;
    d_hg[(size_t)g * DD + d] = acc / (float)c;
}

// ==================== output MLP ====================
__global__ void out_kernel(float* __restrict__ outp,
                           const float* __restrict__ ow1, const float* __restrict__ ob1,
                           const float* __restrict__ ow2, const float* __restrict__ ob2) {
    int g = blockIdx.x;
    int t = threadIdx.x;
    __shared__ float sp[128];
    const float* row = d_hg + (size_t)g * DD;
    float acc = ob1[t];
    for (int k = 0; k < DD; k++) acc = fmaf(row[k], ow1[t * DD + k], acc);
    float v = (acc > 20.f) ? acc : log1pf(expf(acc));
    sp[t] = v;
    __syncthreads();
    if (t < 2) {
        float o = ob2[t];
        for (int k = 0; k < 128; k++) o = fmaf(sp[k], ow2[t * 128 + k], o);
        outp[g * 2 + t] = o;
    }
}

// ==================== launch ====================
extern "C" void kernel_launch(void* const* d_in, const int* in_sizes, int n_in,
                              void* d_out, int out_size) {
    const int* xf = (const int*)d_in[0];
    const int* ei = (const int*)d_in[1];
    const int* ea = (const int*)d_in[2];
    const int* batch = (const int*)d_in[3];
    const float* nt1 = (const float*)d_in[4];
    const float* nt2 = (const float*)d_in[5];
    const float* nt3 = (const float*)d_in[6];
    const float* nt4 = (const float*)d_in[7];
    const float* nt5 = (const float*)d_in[8];
    const float* nt6 = (const float*)d_in[9];
    const float* et1 = (const float*)d_in[10];
    const float* et2 = (const float*)d_in[11];
    const float* et3 = (const float*)d_in[12];
    const float* et4 = (const float*)d_in[13];
    const float* et5 = (const float*)d_in[14];
    const float* w1 = (const float*)d_in[15];
    const float* b1 = (const float*)d_in[16];
    const float* w2 = (const float*)d_in[17];
    const float* b2 = (const float*)d_in[18];
    const float* bng = (const float*)d_in[19];
    const float* bnb = (const float*)d_in[20];
    const float* pw = (const float*)d_in[21];
    const float* pg = (const float*)d_in[22];
    const float* pb = (const float*)d_in[23];
    const float* ow1 = (const float*)d_in[24];
    const float* ob1 = (const float*)d_in[25];
    const float* ow2 = (const float*)d_in[26];
    const float* ob2 = (const float*)d_in[27];
    float* outp = (float*)d_out;

    float *p_h, *p_hh, *p_hg, *p_hg2, *p_ctab;
    __half *p_ahi, *p_alo, *p_hhi, *p_hlo, *p_w1hi, *p_w1lo, *p_w2hi, *p_w2lo;
    cudaGetSymbolAddress((void**)&p_h, d_h);
    cudaGetSymbolAddress((void**)&p_hh, d_hh);
    cudaGetSymbolAddress((void**)&p_hg, d_hg);
    cudaGetSymbolAddress((void**)&p_hg2, d_hg2);
    cudaGetSymbolAddress((void**)&p_ctab, d_ctab);
    cudaGetSymbolAddress((void**)&p_ahi, d_aggr_hi);
    cudaGetSymbolAddress((void**)&p_alo, d_aggr_lo);
    cudaGetSymbolAddress((void**)&p_hhi, d_hid_hi);
    cudaGetSymbolAddress((void**)&p_hlo, d_hid_lo);
    cudaGetSymbolAddress((void**)&p_w1hi, d_w1hi);
    cudaGetSymbolAddress((void**)&p_w1lo, d_w1lo);
    cudaGetSymbolAddress((void**)&p_w2hi, d_w2hi);
    cudaGetSymbolAddress((void**)&p_w2lo, d_w2lo);

    cudaFuncSetAttribute(gemm_hmma<0>, cudaFuncAttributeMaxDynamicSharedMemorySize, GSMEM);
    cudaFuncSetAttribute(gemm_hmma<1>, cudaFuncAttributeMaxDynamicSharedMemorySize, GSMEM);

    embed_kernel<<<NN, DD>>>(xf, nt1, nt2, nt3, nt4, nt5, nt6);

    const int WN = LL * 2 * DD * DD;
    wconv_kernel<<<(2 * WN + 255) / 256, 256>>>(w1, w2, p_w1hi, p_w1lo, p_w2hi, p_w2lo, WN);

    ctab_all_kernel<<<LL * 33, DD>>>(et1, et2, et3, et4, et5);

    const int SBLK = (NN + 1023) / 1024;  // 20
    count_kernel<<<(EE + 255) / 256, 256>>>(ei);
    scan1_kernel<<<SBLK, 1024>>>();
    scan2_kernel<<<1, 32>>>(SBLK);
    scan3_kernel<<<SBLK, 1024>>>();
    fill_kernel<<<(EE + 255) / 256, 256>>>(ei, ea);

    const int GY = (NN + 127) / 128;  // 157
    for (int l = 0; l < LL; l++) {
        const float* ctab_l = p_ctab + (size_t)l * 33 * DD;
        if (l == 0)
            spmm_kernel<0><<<NN / 8, 256>>>(p_h, ctab_l);
        else
            spmm_kernel<1><<<NN / 8, 256>>>(p_hh, ctab_l);
        gemm_hmma<0><<<dim3(4, GY), 256, GSMEM>>>(
            nullptr, p_hhi, p_hlo, p_ahi, p_alo,
            p_w1hi + (size_t)l * 2 * DD * DD, p_w1lo + (size_t)l * 2 * DD * DD,
            b1 + (size_t)l * 2 * DD, NN, DD, 2 * DD, 1);
        gemm_hmma<1><<<dim3(2, GY), 256, GSMEM>>>(
            p_hh, nullptr, nullptr, p_hhi, p_hlo,
            p_w2hi + (size_t)l * 2 * DD * DD, p_w2lo + (size_t)l * 2 * DD * DD,
            b2 + (size_t)l * DD, NN, 2 * DD, DD, 0);
        colstats_fused<<<(NN + 127) / 128, DD>>>(p_hh, NN,
                                                 bng + (size_t)l * DD, bnb + (size_t)l * DD);
    }

    pool_kernel<<<GG, DD>>>(batch);

    for (int i = 0; i < 3; i++) {
        gemm64s<<<dim3(4, 4), 256>>>(p_hg2, p_hg, pw + (size_t)i * DD * DD, GG, DD, DD);
        bn_affine_proj<<<GG, DD>>>(p_hg, p_hg2, pg + (size_t)i * DD, pb + (size_t)i * DD,
                                   (i < 2) ? 1 : 0);
    }

    out_kernel<<<GG, 128>>>(outp, ow1, ob1, ow2, ob2);
}